// round 1
// baseline (speedup 1.0000x reference)
#include <cuda_runtime.h>
#include <cuda_bf16.h>
#include <math_constants.h>

// Problem constants
#define B_TOT   2048
#define NSEQ    49
#define CDIM    256
#define NHEADS  8
#define DHEAD   32
#define NW      64
#define THREECD 768

// Scratch (allocation-free rule: __device__ globals)
__device__ float g_qkv[(size_t)B_TOT * NSEQ * THREECD];     // [B, N, 3C] ~308MB
__device__ float g_attnout[(size_t)B_TOT * NSEQ * CDIM];    // [B, N, C]  ~102MB

// ---------------------------------------------------------------------------
// Tiled SGEMM: C[M,N] = A[M,K] @ B[K,N] + bias[N]
// BM=BN=64, BK=16, 256 threads, 4x4 per thread. Assumes M%64==0, N%64==0, K%16==0.
// ---------------------------------------------------------------------------
#define BM 64
#define BN 64
#define BK 16

__global__ __launch_bounds__(256) void gemm_bias_kernel(
    const float* __restrict__ A, const float* __restrict__ B,
    const float* __restrict__ bias, float* __restrict__ C,
    int M, int K, int N)
{
    __shared__ float As[BK][BM + 4];  // transposed A tile, padded
    __shared__ float Bs[BK][BN];

    const int tid = threadIdx.x;
    const int tr  = tid >> 4;   // 0..15
    const int tc  = tid & 15;   // 0..15
    const int blockRow = blockIdx.y * BM;
    const int blockCol = blockIdx.x * BN;

    float acc[4][4];
#pragma unroll
    for (int i = 0; i < 4; i++)
#pragma unroll
        for (int j = 0; j < 4; j++) acc[i][j] = 0.f;

    // loader mapping
    const int a_m  = tid >> 2;          // 0..63
    const int a_k4 = (tid & 3) << 2;    // 0,4,8,12
    const int b_k  = tid >> 4;          // 0..15
    const int b_n4 = (tid & 15) << 2;   // 0..60

    for (int k0 = 0; k0 < K; k0 += BK) {
        // load A tile 64x16, store transposed
        float4 av = *reinterpret_cast<const float4*>(
            &A[(size_t)(blockRow + a_m) * K + k0 + a_k4]);
        As[a_k4 + 0][a_m] = av.x;
        As[a_k4 + 1][a_m] = av.y;
        As[a_k4 + 2][a_m] = av.z;
        As[a_k4 + 3][a_m] = av.w;
        // load B tile 16x64
        float4 bv = *reinterpret_cast<const float4*>(
            &B[(size_t)(k0 + b_k) * N + blockCol + b_n4]);
        *reinterpret_cast<float4*>(&Bs[b_k][b_n4]) = bv;
        __syncthreads();

#pragma unroll
        for (int kk = 0; kk < BK; kk++) {
            float rm[4], rn[4];
#pragma unroll
            for (int i = 0; i < 4; i++) rm[i] = As[kk][tr * 4 + i];
            float4 nv = *reinterpret_cast<const float4*>(&Bs[kk][tc * 4]);
            rn[0] = nv.x; rn[1] = nv.y; rn[2] = nv.z; rn[3] = nv.w;
#pragma unroll
            for (int i = 0; i < 4; i++)
#pragma unroll
                for (int j = 0; j < 4; j++)
                    acc[i][j] = fmaf(rm[i], rn[j], acc[i][j]);
        }
        __syncthreads();
    }

    // epilogue with bias
    float bb[4];
#pragma unroll
    for (int j = 0; j < 4; j++) bb[j] = bias[blockCol + tc * 4 + j];
#pragma unroll
    for (int i = 0; i < 4; i++) {
        float4 ov;
        ov.x = acc[i][0] + bb[0];
        ov.y = acc[i][1] + bb[1];
        ov.z = acc[i][2] + bb[2];
        ov.w = acc[i][3] + bb[3];
        *reinterpret_cast<float4*>(
            &C[(size_t)(blockRow + tr * 4 + i) * N + blockCol + tc * 4]) = ov;
    }
}

// ---------------------------------------------------------------------------
// Fused window attention: one CTA per (b, h).
// Loads q,k,v [49,32] to smem, computes 49x49 scores with scale+bias+mask,
// row softmax, then attn @ v, writes to g_attnout in [B, N, h*d] layout.
// ---------------------------------------------------------------------------
__global__ __launch_bounds__(128) void attn_kernel(
    const float* __restrict__ qkv, const float* __restrict__ mask,
    const float* __restrict__ bias_table, float* __restrict__ out)
{
    const int h = blockIdx.x;   // 0..7
    const int b = blockIdx.y;   // 0..2047

    __shared__ float qs[NSEQ][DHEAD + 1];
    __shared__ float ks[NSEQ][DHEAD + 1];
    __shared__ float vs[NSEQ][DHEAD + 1];
    __shared__ float sc[NSEQ][NSEQ + 1];

    const float* base = qkv + (size_t)b * NSEQ * THREECD + h * DHEAD;
    for (int e = threadIdx.x; e < NSEQ * DHEAD; e += blockDim.x) {
        int n = e >> 5, dd = e & 31;
        const float* row = base + (size_t)n * THREECD;
        qs[n][dd] = row[dd];
        ks[n][dd] = row[CDIM + dd];
        vs[n][dd] = row[2 * CDIM + dd];
    }
    __syncthreads();

    const int w = b & (NW - 1);
    const float* mrow = mask + (size_t)w * NSEQ * NSEQ;
    const float scale = 0.17677669529663687f;  // 32^-0.5

    for (int p = threadIdx.x; p < NSEQ * NSEQ; p += blockDim.x) {
        int i = p / NSEQ, j = p - i * NSEQ;
        float a = 0.f;
#pragma unroll
        for (int dd = 0; dd < DHEAD; dd++) a = fmaf(qs[i][dd], ks[j][dd], a);
        int i0 = i / 7, i1 = i - i0 * 7;
        int j0 = j / 7, j1 = j - j0 * 7;
        int ridx = (i0 - j0 + 6) * 13 + (i1 - j1 + 6);
        sc[i][j] = fmaf(a, scale, bias_table[ridx * NHEADS + h] + mrow[p]);
    }
    __syncthreads();

    // row softmax: one thread per row
    if (threadIdx.x < NSEQ) {
        int i = threadIdx.x;
        float mx = -CUDART_INF_F;
#pragma unroll 7
        for (int j = 0; j < NSEQ; j++) mx = fmaxf(mx, sc[i][j]);
        float s = 0.f;
#pragma unroll 7
        for (int j = 0; j < NSEQ; j++) {
            float e = __expf(sc[i][j] - mx);
            sc[i][j] = e;
            s += e;
        }
        float inv = 1.f / s;
#pragma unroll 7
        for (int j = 0; j < NSEQ; j++) sc[i][j] *= inv;
    }
    __syncthreads();

    // out[i][dd] = sum_j sc[i][j] * v[j][dd]
    float* obase = out + (size_t)b * NSEQ * CDIM + h * DHEAD;
    for (int e = threadIdx.x; e < NSEQ * DHEAD; e += blockDim.x) {
        int i = e >> 5, dd = e & 31;
        float a = 0.f;
#pragma unroll 7
        for (int j = 0; j < NSEQ; j++) a = fmaf(sc[i][j], vs[j][dd], a);
        obase[(size_t)i * CDIM + dd] = a;
    }
}

// ---------------------------------------------------------------------------
extern "C" void kernel_launch(void* const* d_in, const int* in_sizes, int n_in,
                              void* d_out, int out_size)
{
    const float* x          = (const float*)d_in[0];  // [2048,49,256]
    const float* mask       = (const float*)d_in[1];  // [64,49,49]
    const float* qkv_w      = (const float*)d_in[2];  // [256,768]
    const float* qkv_b      = (const float*)d_in[3];  // [768]
    const float* proj_w     = (const float*)d_in[4];  // [256,256]
    const float* proj_b     = (const float*)d_in[5];  // [256]
    const float* bias_table = (const float*)d_in[6];  // [169,8]
    float* out = (float*)d_out;

    float* qkv_ptr = nullptr;
    float* ao_ptr  = nullptr;
    cudaGetSymbolAddress((void**)&qkv_ptr, g_qkv);
    cudaGetSymbolAddress((void**)&ao_ptr, g_attnout);

    const int M = B_TOT * NSEQ;  // 100352

    // 1) qkv = x @ qkv_w + qkv_b
    {
        dim3 grid(THREECD / BN, M / BM);
        gemm_bias_kernel<<<grid, 256>>>(x, qkv_w, qkv_b, qkv_ptr, M, CDIM, THREECD);
    }
    // 2) window attention
    {
        dim3 grid(NHEADS, B_TOT);
        attn_kernel<<<grid, 128>>>(qkv_ptr, mask, bias_table, ao_ptr);
    }
    // 3) out = attnout @ proj_w + proj_b
    {
        dim3 grid(CDIM / BN, M / BM);
        gemm_bias_kernel<<<grid, 256>>>(ao_ptr, proj_w, proj_b, out, M, CDIM, CDIM);
    }
}

// round 2
// speedup vs baseline: 2.0133x; 2.0133x over previous
#include <cuda_runtime.h>
#include <cuda_bf16.h>
#include <math_constants.h>

// Problem constants
#define B_TOT   2048
#define NSEQ    49
#define CDIM    256
#define NHEADS  8
#define DHEAD   32
#define NW      64
#define THREECD 768

// Scratch (allocation-free rule: __device__ globals)
__device__ float g_qkv[(size_t)B_TOT * NSEQ * THREECD];     // [B, N, 3C]
__device__ float g_attnout[(size_t)B_TOT * NSEQ * CDIM];    // [B, N, C]

// ---------------------------------------------------------------------------
// TF32 tensor-core GEMM: C[M,N] = A[M,K] @ B[K,N] + bias[N]
// CTA tile 128x128, BK=16, 256 threads (8 warps, 4x2), warp tile 32x64.
// mma.sync.aligned.m16n8k8.row.col.f32.tf32.tf32.f32
// Requires M%128==0, N%128==0, K%16==0.
// ---------------------------------------------------------------------------
#define GBM 128
#define GBN 128
#define GBK 16
#define ASTR 20     // 16 + 4 pad (stride in floats, 80B: 16B-aligned rows)
#define BSTR 136    // 128 + 8 pad (544B rows, 16B-aligned; conflict-free b-frag)

__device__ __forceinline__ float to_tf32(float x) {
    unsigned u = __float_as_uint(x);
    asm("cvt.rna.tf32.f32 %0, %1;" : "=r"(u) : "r"(u));
    return __uint_as_float(u);
}

__device__ __forceinline__ void mma_tf32(float (&c)[4], const unsigned (&a)[4],
                                         unsigned b0, unsigned b1) {
    asm volatile(
        "mma.sync.aligned.m16n8k8.row.col.f32.tf32.tf32.f32 "
        "{%0,%1,%2,%3}, {%4,%5,%6,%7}, {%8,%9}, {%0,%1,%2,%3};\n"
        : "+f"(c[0]), "+f"(c[1]), "+f"(c[2]), "+f"(c[3])
        : "r"(a[0]), "r"(a[1]), "r"(a[2]), "r"(a[3]), "r"(b0), "r"(b1));
}

__global__ __launch_bounds__(256, 2) void gemm_tf32_kernel(
    const float* __restrict__ A, const float* __restrict__ B,
    const float* __restrict__ bias, float* __restrict__ C,
    int M, int K, int N)
{
    __shared__ float As[2][GBM][ASTR];   // 2*128*20*4  = 20480 B
    __shared__ float Bs[2][GBK][BSTR];   // 2*16*136*4  = 17408 B

    const int tid  = threadIdx.x;
    const int wid  = tid >> 5;
    const int lane = tid & 31;
    const int wm   = wid & 3;       // 0..3 -> m offset
    const int wn   = wid >> 2;      // 0..1 -> n offset
    const int g    = lane >> 2;     // 0..7
    const int t    = lane & 3;      // 0..3
    const int rowC = blockIdx.y * GBM;
    const int colC = blockIdx.x * GBN;

    const float* Aptr = A + (size_t)rowC * K;
    const float* Bptr = B + colC;

    float acc[2][8][4];
#pragma unroll
    for (int mt = 0; mt < 2; mt++)
#pragma unroll
        for (int nt = 0; nt < 8; nt++)
#pragma unroll
            for (int r = 0; r < 4; r++) acc[mt][nt][r] = 0.f;

    float4 a_st[2], b_st[2];
    const int a_r0 = tid >> 2,        a_c0 = (tid & 3) * 4;
    const int a_r1 = (tid + 256) >> 2, a_c1 = ((tid + 256) & 3) * 4;
    const int b_r0 = tid >> 5,        b_c0 = (tid & 31) * 4;
    const int b_r1 = (tid + 256) >> 5, b_c1 = ((tid + 256) & 31) * 4;

    // ---- prologue: load tile 0
    {
        const int k0 = 0;
        a_st[0] = *(const float4*)(Aptr + (size_t)a_r0 * K + k0 + a_c0);
        a_st[1] = *(const float4*)(Aptr + (size_t)a_r1 * K + k0 + a_c1);
        b_st[0] = *(const float4*)(Bptr + (size_t)(k0 + b_r0) * N + b_c0);
        b_st[1] = *(const float4*)(Bptr + (size_t)(k0 + b_r1) * N + b_c1);
        float4 v;
        v.x = to_tf32(a_st[0].x); v.y = to_tf32(a_st[0].y);
        v.z = to_tf32(a_st[0].z); v.w = to_tf32(a_st[0].w);
        *(float4*)&As[0][a_r0][a_c0] = v;
        v.x = to_tf32(a_st[1].x); v.y = to_tf32(a_st[1].y);
        v.z = to_tf32(a_st[1].z); v.w = to_tf32(a_st[1].w);
        *(float4*)&As[0][a_r1][a_c1] = v;
        v.x = to_tf32(b_st[0].x); v.y = to_tf32(b_st[0].y);
        v.z = to_tf32(b_st[0].z); v.w = to_tf32(b_st[0].w);
        *(float4*)&Bs[0][b_r0][b_c0] = v;
        v.x = to_tf32(b_st[1].x); v.y = to_tf32(b_st[1].y);
        v.z = to_tf32(b_st[1].z); v.w = to_tf32(b_st[1].w);
        *(float4*)&Bs[0][b_r1][b_c1] = v;
    }
    __syncthreads();

    const int nk = K / GBK;
    int buf = 0;
    for (int kt = 0; kt < nk; kt++) {
        if (kt + 1 < nk) {
            const int k0 = (kt + 1) * GBK;
            a_st[0] = *(const float4*)(Aptr + (size_t)a_r0 * K + k0 + a_c0);
            a_st[1] = *(const float4*)(Aptr + (size_t)a_r1 * K + k0 + a_c1);
            b_st[0] = *(const float4*)(Bptr + (size_t)(k0 + b_r0) * N + b_c0);
            b_st[1] = *(const float4*)(Bptr + (size_t)(k0 + b_r1) * N + b_c1);
        }

        // ---- compute on buffer `buf`
#pragma unroll
        for (int s = 0; s < 2; s++) {
            const int k8 = s * 8;
            unsigned af[2][4];
#pragma unroll
            for (int mt = 0; mt < 2; mt++) {
                const int row = wm * 32 + mt * 16;
                af[mt][0] = __float_as_uint(As[buf][row + g][k8 + t]);
                af[mt][1] = __float_as_uint(As[buf][row + g + 8][k8 + t]);
                af[mt][2] = __float_as_uint(As[buf][row + g][k8 + t + 4]);
                af[mt][3] = __float_as_uint(As[buf][row + g + 8][k8 + t + 4]);
            }
#pragma unroll
            for (int nt = 0; nt < 8; nt++) {
                const int col = wn * 64 + nt * 8 + g;
                unsigned b0 = __float_as_uint(Bs[buf][k8 + t][col]);
                unsigned b1 = __float_as_uint(Bs[buf][k8 + t + 4][col]);
                mma_tf32(acc[0][nt], af[0], b0, b1);
                mma_tf32(acc[1][nt], af[1], b0, b1);
            }
        }

        if (kt + 1 < nk) {
            const int nb = buf ^ 1;
            float4 v;
            v.x = to_tf32(a_st[0].x); v.y = to_tf32(a_st[0].y);
            v.z = to_tf32(a_st[0].z); v.w = to_tf32(a_st[0].w);
            *(float4*)&As[nb][a_r0][a_c0] = v;
            v.x = to_tf32(a_st[1].x); v.y = to_tf32(a_st[1].y);
            v.z = to_tf32(a_st[1].z); v.w = to_tf32(a_st[1].w);
            *(float4*)&As[nb][a_r1][a_c1] = v;
            v.x = to_tf32(b_st[0].x); v.y = to_tf32(b_st[0].y);
            v.z = to_tf32(b_st[0].z); v.w = to_tf32(b_st[0].w);
            *(float4*)&Bs[nb][b_r0][b_c0] = v;
            v.x = to_tf32(b_st[1].x); v.y = to_tf32(b_st[1].y);
            v.z = to_tf32(b_st[1].z); v.w = to_tf32(b_st[1].w);
            *(float4*)&Bs[nb][b_r1][b_c1] = v;
            __syncthreads();
            buf = nb;
        }
    }

    // ---- epilogue: bias + store (float2 per fragment row)
#pragma unroll
    for (int mt = 0; mt < 2; mt++) {
        const int r0 = rowC + wm * 32 + mt * 16 + g;
#pragma unroll
        for (int nt = 0; nt < 8; nt++) {
            const int cc = colC + wn * 64 + nt * 8 + 2 * t;
            const float bb0 = bias[cc], bb1 = bias[cc + 1];
            float2 o;
            o.x = acc[mt][nt][0] + bb0;
            o.y = acc[mt][nt][1] + bb1;
            *(float2*)&C[(size_t)r0 * N + cc] = o;
            o.x = acc[mt][nt][2] + bb0;
            o.y = acc[mt][nt][3] + bb1;
            *(float2*)&C[(size_t)(r0 + 8) * N + cc] = o;
        }
    }
}

// ---------------------------------------------------------------------------
// Fused window attention: one CTA per (b, h), 128 threads.
// ---------------------------------------------------------------------------
__global__ __launch_bounds__(128) void attn_kernel(
    const float* __restrict__ qkv, const float* __restrict__ mask,
    const float* __restrict__ bias_table, float* __restrict__ out)
{
    const int h = blockIdx.x;   // 0..7
    const int b = blockIdx.y;   // 0..2047

    __shared__ float qs[NSEQ][36];
    __shared__ float ks[NSEQ][36];
    __shared__ float vs[NSEQ][36];
    __shared__ float sc[NSEQ][52];

    const int tid  = threadIdx.x;
    const int lane = tid & 31;
    const int wrp  = tid >> 5;
    const float scale = 0.17677669529663687f;  // 32^-0.5

    const float* base = qkv + (size_t)b * NSEQ * THREECD + h * DHEAD;
    for (int f = tid; f < NSEQ * 8; f += 128) {
        int n = f >> 3, c = (f & 7) * 4;
        const float* row = base + (size_t)n * THREECD;
        float4 q4 = *(const float4*)(row + c);
        float4 k4 = *(const float4*)(row + CDIM + c);
        float4 v4 = *(const float4*)(row + 2 * CDIM + c);
        q4.x *= scale; q4.y *= scale; q4.z *= scale; q4.w *= scale;
        *(float4*)&qs[n][c] = q4;
        *(float4*)&ks[n][c] = k4;
        *(float4*)&vs[n][c] = v4;
    }
    __syncthreads();

    const int w = b & (NW - 1);
    const float* mrow = mask + (size_t)w * NSEQ * NSEQ;

    for (int p = tid; p < NSEQ * NSEQ; p += 128) {
        int i = p / NSEQ, j = p - i * NSEQ;
        float a = 0.f;
#pragma unroll
        for (int c = 0; c < DHEAD; c += 4) {
            float4 q = *(const float4*)&qs[i][c];
            float4 k = *(const float4*)&ks[j][c];
            a = fmaf(q.x, k.x, a);
            a = fmaf(q.y, k.y, a);
            a = fmaf(q.z, k.z, a);
            a = fmaf(q.w, k.w, a);
        }
        int i0 = i / 7, i1 = i - i0 * 7;
        int j0 = j / 7, j1 = j - j0 * 7;
        int ridx = (i0 - j0 + 6) * 13 + (i1 - j1 + 6);
        sc[i][j] = a + bias_table[ridx * NHEADS + h] + mrow[p];
    }
    __syncthreads();

    // warp-per-row softmax (4 warps cycle over 49 rows)
    for (int i = wrp; i < NSEQ; i += 4) {
        float v0 = sc[i][lane];
        float v1 = (lane + 32 < NSEQ) ? sc[i][lane + 32] : -CUDART_INF_F;
        float m = fmaxf(v0, v1);
#pragma unroll
        for (int o = 16; o > 0; o >>= 1)
            m = fmaxf(m, __shfl_xor_sync(0xffffffffu, m, o));
        float e0 = __expf(v0 - m);
        float e1 = (lane + 32 < NSEQ) ? __expf(v1 - m) : 0.f;
        float s = e0 + e1;
#pragma unroll
        for (int o = 16; o > 0; o >>= 1)
            s += __shfl_xor_sync(0xffffffffu, s, o);
        float inv = 1.f / s;
        sc[i][lane] = e0 * inv;
        if (lane + 32 < NSEQ) sc[i][lane + 32] = e1 * inv;
    }
    __syncthreads();

    // out[i][dd] = sum_j sc[i][j] * v[j][dd]
    float* obase = out + (size_t)b * NSEQ * CDIM + h * DHEAD;
    for (int e = tid; e < NSEQ * DHEAD; e += 128) {
        int i = e >> 5, dd = e & 31;
        float a = 0.f;
#pragma unroll 7
        for (int j = 0; j < NSEQ; j++) a = fmaf(sc[i][j], vs[j][dd], a);
        obase[(size_t)i * CDIM + dd] = a;
    }
}

// ---------------------------------------------------------------------------
extern "C" void kernel_launch(void* const* d_in, const int* in_sizes, int n_in,
                              void* d_out, int out_size)
{
    const float* x          = (const float*)d_in[0];  // [2048,49,256]
    const float* mask       = (const float*)d_in[1];  // [64,49,49]
    const float* qkv_w      = (const float*)d_in[2];  // [256,768]
    const float* qkv_b      = (const float*)d_in[3];  // [768]
    const float* proj_w     = (const float*)d_in[4];  // [256,256]
    const float* proj_b     = (const float*)d_in[5];  // [256]
    const float* bias_table = (const float*)d_in[6];  // [169,8]
    float* out = (float*)d_out;

    float* qkv_ptr = nullptr;
    float* ao_ptr  = nullptr;
    cudaGetSymbolAddress((void**)&qkv_ptr, g_qkv);
    cudaGetSymbolAddress((void**)&ao_ptr, g_attnout);

    const int M = B_TOT * NSEQ;  // 100352

    // 1) qkv = x @ qkv_w + qkv_b     (TF32 tensor cores)
    {
        dim3 grid(THREECD / GBN, M / GBM);
        gemm_tf32_kernel<<<grid, 256>>>(x, qkv_w, qkv_b, qkv_ptr, M, CDIM, THREECD);
    }
    // 2) window attention
    {
        dim3 grid(NHEADS, B_TOT);
        attn_kernel<<<grid, 128>>>(qkv_ptr, mask, bias_table, ao_ptr);
    }
    // 3) out = attnout @ proj_w + proj_b   (TF32 tensor cores)
    {
        dim3 grid(CDIM / GBN, M / GBM);
        gemm_tf32_kernel<<<grid, 256>>>(ao_ptr, proj_w, proj_b, out, M, CDIM, CDIM);
    }
}

// round 3
// speedup vs baseline: 2.9194x; 1.4501x over previous
#include <cuda_runtime.h>
#include <cuda_bf16.h>
#include <math_constants.h>

// Problem constants
#define B_TOT   2048
#define NSEQ    49
#define CDIM    256
#define NHEADS  8
#define DHEAD   32
#define NW      64
#define THREECD 768

// Scratch (allocation-free rule: __device__ globals)
__device__ float g_qkv[(size_t)B_TOT * NSEQ * THREECD];     // [B, N, 3C]
__device__ float g_attnout[(size_t)B_TOT * NSEQ * CDIM];    // [B, N, C]

__device__ __forceinline__ float to_tf32(float x) {
    unsigned u = __float_as_uint(x);
    asm("cvt.rna.tf32.f32 %0, %1;" : "=r"(u) : "r"(u));
    return __uint_as_float(u);
}

__device__ __forceinline__ void mma_tf32(float (&c)[4], const unsigned (&a)[4],
                                         unsigned b0, unsigned b1) {
    asm volatile(
        "mma.sync.aligned.m16n8k8.row.col.f32.tf32.tf32.f32 "
        "{%0,%1,%2,%3}, {%4,%5,%6,%7}, {%8,%9}, {%0,%1,%2,%3};\n"
        : "+f"(c[0]), "+f"(c[1]), "+f"(c[2]), "+f"(c[3])
        : "r"(a[0]), "r"(a[1]), "r"(a[2]), "r"(a[3]), "r"(b0), "r"(b1));
}

// ---------------------------------------------------------------------------
// TF32 tensor-core GEMM: C[M,N] = A[M,K] @ B[K,N] + bias[N]
// CTA tile 128x128, BK=16, 256 threads (8 warps, 4x2), warp tile 32x64.
// ---------------------------------------------------------------------------
#define GBM 128
#define GBN 128
#define GBK 16
#define ASTR 20
#define BSTR 136

__global__ __launch_bounds__(256, 2) void gemm_tf32_kernel(
    const float* __restrict__ A, const float* __restrict__ B,
    const float* __restrict__ bias, float* __restrict__ C,
    int M, int K, int N)
{
    __shared__ float As[2][GBM][ASTR];
    __shared__ float Bs[2][GBK][BSTR];

    const int tid  = threadIdx.x;
    const int wid  = tid >> 5;
    const int lane = tid & 31;
    const int wm   = wid & 3;
    const int wn   = wid >> 2;
    const int g    = lane >> 2;
    const int t    = lane & 3;
    const int rowC = blockIdx.y * GBM;
    const int colC = blockIdx.x * GBN;

    const float* Aptr = A + (size_t)rowC * K;
    const float* Bptr = B + colC;

    float acc[2][8][4];
#pragma unroll
    for (int mt = 0; mt < 2; mt++)
#pragma unroll
        for (int nt = 0; nt < 8; nt++)
#pragma unroll
            for (int r = 0; r < 4; r++) acc[mt][nt][r] = 0.f;

    float4 a_st[2], b_st[2];
    const int a_r0 = tid >> 2,         a_c0 = (tid & 3) * 4;
    const int a_r1 = (tid + 256) >> 2, a_c1 = ((tid + 256) & 3) * 4;
    const int b_r0 = tid >> 5,         b_c0 = (tid & 31) * 4;
    const int b_r1 = (tid + 256) >> 5, b_c1 = ((tid + 256) & 31) * 4;

    {
        a_st[0] = *(const float4*)(Aptr + (size_t)a_r0 * K + a_c0);
        a_st[1] = *(const float4*)(Aptr + (size_t)a_r1 * K + a_c1);
        b_st[0] = *(const float4*)(Bptr + (size_t)b_r0 * N + b_c0);
        b_st[1] = *(const float4*)(Bptr + (size_t)b_r1 * N + b_c1);
        float4 v;
        v.x = to_tf32(a_st[0].x); v.y = to_tf32(a_st[0].y);
        v.z = to_tf32(a_st[0].z); v.w = to_tf32(a_st[0].w);
        *(float4*)&As[0][a_r0][a_c0] = v;
        v.x = to_tf32(a_st[1].x); v.y = to_tf32(a_st[1].y);
        v.z = to_tf32(a_st[1].z); v.w = to_tf32(a_st[1].w);
        *(float4*)&As[0][a_r1][a_c1] = v;
        v.x = to_tf32(b_st[0].x); v.y = to_tf32(b_st[0].y);
        v.z = to_tf32(b_st[0].z); v.w = to_tf32(b_st[0].w);
        *(float4*)&Bs[0][b_r0][b_c0] = v;
        v.x = to_tf32(b_st[1].x); v.y = to_tf32(b_st[1].y);
        v.z = to_tf32(b_st[1].z); v.w = to_tf32(b_st[1].w);
        *(float4*)&Bs[0][b_r1][b_c1] = v;
    }
    __syncthreads();

    const int nk = K / GBK;
    int buf = 0;
    for (int kt = 0; kt < nk; kt++) {
        if (kt + 1 < nk) {
            const int k0 = (kt + 1) * GBK;
            a_st[0] = *(const float4*)(Aptr + (size_t)a_r0 * K + k0 + a_c0);
            a_st[1] = *(const float4*)(Aptr + (size_t)a_r1 * K + k0 + a_c1);
            b_st[0] = *(const float4*)(Bptr + (size_t)(k0 + b_r0) * N + b_c0);
            b_st[1] = *(const float4*)(Bptr + (size_t)(k0 + b_r1) * N + b_c1);
        }

#pragma unroll
        for (int s = 0; s < 2; s++) {
            const int k8 = s * 8;
            unsigned af[2][4];
#pragma unroll
            for (int mt = 0; mt < 2; mt++) {
                const int row = wm * 32 + mt * 16;
                af[mt][0] = __float_as_uint(As[buf][row + g][k8 + t]);
                af[mt][1] = __float_as_uint(As[buf][row + g + 8][k8 + t]);
                af[mt][2] = __float_as_uint(As[buf][row + g][k8 + t + 4]);
                af[mt][3] = __float_as_uint(As[buf][row + g + 8][k8 + t + 4]);
            }
#pragma unroll
            for (int nt = 0; nt < 8; nt++) {
                const int col = wn * 64 + nt * 8 + g;
                unsigned b0 = __float_as_uint(Bs[buf][k8 + t][col]);
                unsigned b1 = __float_as_uint(Bs[buf][k8 + t + 4][col]);
                mma_tf32(acc[0][nt], af[0], b0, b1);
                mma_tf32(acc[1][nt], af[1], b0, b1);
            }
        }

        if (kt + 1 < nk) {
            const int nb = buf ^ 1;
            float4 v;
            v.x = to_tf32(a_st[0].x); v.y = to_tf32(a_st[0].y);
            v.z = to_tf32(a_st[0].z); v.w = to_tf32(a_st[0].w);
            *(float4*)&As[nb][a_r0][a_c0] = v;
            v.x = to_tf32(a_st[1].x); v.y = to_tf32(a_st[1].y);
            v.z = to_tf32(a_st[1].z); v.w = to_tf32(a_st[1].w);
            *(float4*)&As[nb][a_r1][a_c1] = v;
            v.x = to_tf32(b_st[0].x); v.y = to_tf32(b_st[0].y);
            v.z = to_tf32(b_st[0].z); v.w = to_tf32(b_st[0].w);
            *(float4*)&Bs[nb][b_r0][b_c0] = v;
            v.x = to_tf32(b_st[1].x); v.y = to_tf32(b_st[1].y);
            v.z = to_tf32(b_st[1].z); v.w = to_tf32(b_st[1].w);
            *(float4*)&Bs[nb][b_r1][b_c1] = v;
            __syncthreads();
            buf = nb;
        }
    }

#pragma unroll
    for (int mt = 0; mt < 2; mt++) {
        const int r0 = rowC + wm * 32 + mt * 16 + g;
#pragma unroll
        for (int nt = 0; nt < 8; nt++) {
            const int cc = colC + wn * 64 + nt * 8 + 2 * t;
            const float bb0 = bias[cc], bb1 = bias[cc + 1];
            float2 o;
            o.x = acc[mt][nt][0] + bb0;
            o.y = acc[mt][nt][1] + bb1;
            *(float2*)&C[(size_t)r0 * N + cc] = o;
            o.x = acc[mt][nt][2] + bb0;
            o.y = acc[mt][nt][3] + bb1;
            *(float2*)&C[(size_t)(r0 + 8) * N + cc] = o;
        }
    }
}

// ---------------------------------------------------------------------------
// Tensor-core window attention: one CTA per (b, h), 4 warps.
// Warp w owns m16 tile w (rows 16w..16w+15) of the padded 64x56 score matrix.
// QK^T via tf32 mma; softmax in fp32 in smem; AV via split-tf32 mma (exact P).
// ---------------------------------------------------------------------------
__global__ __launch_bounds__(128) void attn_mma_kernel(
    const float* __restrict__ qkv, const float* __restrict__ mask,
    const float* __restrict__ bias_table, float* __restrict__ out)
{
    const int h = blockIdx.x;   // 0..7
    const int b = blockIdx.y;   // 0..2047

    __shared__ float qs[64][36];   // q (scaled, tf32), bank = 4g+t
    __shared__ float ks[56][36];   // k natural [j][d]; B-frag ks[col][k]
    __shared__ float vs[56][40];   // v (tf32) [j][d]; bank = 8t+g
    __shared__ float sc[64][68];   // scores -> probabilities

    const int tid  = threadIdx.x;
    const int lane = tid & 31;
    const int wid  = tid >> 5;   // m-tile
    const int g    = lane >> 2;  // 0..7
    const int t    = lane & 3;   // 0..3
    const float scale = 0.17677669529663687f;  // 32^-0.5

    // ---- load q,k,v (tf32-converted; q pre-scaled)
    const float* base = qkv + (size_t)b * NSEQ * THREECD + h * DHEAD;
    for (int f = tid; f < NSEQ * 8; f += 128) {
        int n = f >> 3, c = (f & 7) << 2;
        const float* row = base + (size_t)n * THREECD;
        float4 q4 = *(const float4*)(row + c);
        float4 k4 = *(const float4*)(row + CDIM + c);
        float4 v4 = *(const float4*)(row + 2 * CDIM + c);
        float4 o;
        o.x = to_tf32(q4.x * scale); o.y = to_tf32(q4.y * scale);
        o.z = to_tf32(q4.z * scale); o.w = to_tf32(q4.w * scale);
        *(float4*)&qs[n][c] = o;
        o.x = to_tf32(k4.x); o.y = to_tf32(k4.y);
        o.z = to_tf32(k4.z); o.w = to_tf32(k4.w);
        *(float4*)&ks[n][c] = o;
        o.x = to_tf32(v4.x); o.y = to_tf32(v4.y);
        o.z = to_tf32(v4.z); o.w = to_tf32(v4.w);
        *(float4*)&vs[n][c] = o;
    }
    // zero v padding rows 49..55 (k-dim padding for AV must not be NaN)
    for (int z = tid; z < 7 * 40; z += 128) vs[NSEQ + z / 40][z % 40] = 0.f;
    __syncthreads();

    const int row = wid * 16;

    // ---- QK^T: scores[row..row+15][0..55]
    float c_sc[7][4];
#pragma unroll
    for (int nt = 0; nt < 7; nt++)
#pragma unroll
        for (int r = 0; r < 4; r++) c_sc[nt][r] = 0.f;

#pragma unroll
    for (int kk = 0; kk < 4; kk++) {
        const int k8 = kk * 8;
        unsigned a[4];
        a[0] = __float_as_uint(qs[row + g][k8 + t]);
        a[1] = __float_as_uint(qs[row + g + 8][k8 + t]);
        a[2] = __float_as_uint(qs[row + g][k8 + t + 4]);
        a[3] = __float_as_uint(qs[row + g + 8][k8 + t + 4]);
#pragma unroll
        for (int nt = 0; nt < 7; nt++) {
            unsigned b0 = __float_as_uint(ks[nt * 8 + g][k8 + t]);
            unsigned b1 = __float_as_uint(ks[nt * 8 + g][k8 + t + 4]);
            mma_tf32(c_sc[nt], a, b0, b1);
        }
    }

    // ---- epilogue: + relative-position bias + mask -> sc (fp32)
    const int w = b & (NW - 1);
    const float* mrow = mask + (size_t)w * NSEQ * NSEQ;
    const int r0 = row + g, r1 = row + g + 8;
    const int i0a = r0 / 7, i1a = r0 - i0a * 7;
    const int i0b = r1 / 7, i1b = r1 - i0b * 7;
#pragma unroll
    for (int nt = 0; nt < 7; nt++) {
        const int c0 = nt * 8 + 2 * t;
#pragma unroll
        for (int cx = 0; cx < 2; cx++) {
            const int cc = c0 + cx;
            if (cc < NSEQ) {
                const int j0 = cc / 7, j1 = cc - j0 * 7;
                if (r0 < NSEQ) {
                    int ridx = (i0a - j0 + 6) * 13 + (i1a - j1 + 6);
                    sc[r0][cc] = c_sc[nt][cx] + bias_table[ridx * NHEADS + h]
                               + mrow[r0 * NSEQ + cc];
                }
                if (r1 < NSEQ) {
                    int ridx = (i0b - j0 + 6) * 13 + (i1b - j1 + 6);
                    sc[r1][cc] = c_sc[nt][2 + cx] + bias_table[ridx * NHEADS + h]
                               + mrow[r1 * NSEQ + cc];
                }
            }
        }
    }
    __syncthreads();

    // ---- softmax: warp per row; also zero pad columns 49..55
    for (int i = wid; i < NSEQ; i += 4) {
        float v0 = sc[i][lane];
        const int c2 = lane + 32;
        float v1 = (c2 < NSEQ) ? sc[i][c2] : -CUDART_INF_F;
        float m = fmaxf(v0, v1);
#pragma unroll
        for (int o = 16; o > 0; o >>= 1)
            m = fmaxf(m, __shfl_xor_sync(0xffffffffu, m, o));
        float e0 = __expf(v0 - m);
        float e1 = (c2 < NSEQ) ? __expf(v1 - m) : 0.f;
        float s = e0 + e1;
#pragma unroll
        for (int o = 16; o > 0; o >>= 1)
            s += __shfl_xor_sync(0xffffffffu, s, o);
        float inv = 1.f / s;
        sc[i][lane] = e0 * inv;
        if (c2 < 56) sc[i][c2] = (c2 < NSEQ) ? e1 * inv : 0.f;
    }
    __syncthreads();

    // ---- AV: out[row..row+15][0..31], split-tf32 on probabilities
    float c_o[4][4];
#pragma unroll
    for (int nt = 0; nt < 4; nt++)
#pragma unroll
        for (int r = 0; r < 4; r++) c_o[nt][r] = 0.f;

#pragma unroll
    for (int kk = 0; kk < 7; kk++) {
        const int k8 = kk * 8;
        float p0 = sc[row + g][k8 + t];
        float p1 = sc[row + g + 8][k8 + t];
        float p2 = sc[row + g][k8 + t + 4];
        float p3 = sc[row + g + 8][k8 + t + 4];
        unsigned ah[4], al[4];
        ah[0] = __float_as_uint(to_tf32(p0));
        ah[1] = __float_as_uint(to_tf32(p1));
        ah[2] = __float_as_uint(to_tf32(p2));
        ah[3] = __float_as_uint(to_tf32(p3));
        al[0] = __float_as_uint(to_tf32(p0 - __uint_as_float(ah[0])));
        al[1] = __float_as_uint(to_tf32(p1 - __uint_as_float(ah[1])));
        al[2] = __float_as_uint(to_tf32(p2 - __uint_as_float(ah[2])));
        al[3] = __float_as_uint(to_tf32(p3 - __uint_as_float(ah[3])));
#pragma unroll
        for (int nt = 0; nt < 4; nt++) {
            unsigned b0 = __float_as_uint(vs[k8 + t][nt * 8 + g]);
            unsigned b1 = __float_as_uint(vs[k8 + t + 4][nt * 8 + g]);
            mma_tf32(c_o[nt], ah, b0, b1);
            mma_tf32(c_o[nt], al, b0, b1);
        }
    }

    // ---- store
    float* obase = out + (size_t)b * NSEQ * CDIM + h * DHEAD;
#pragma unroll
    for (int nt = 0; nt < 4; nt++) {
        const int dd = nt * 8 + 2 * t;
        if (r0 < NSEQ) {
            float2 o; o.x = c_o[nt][0]; o.y = c_o[nt][1];
            *(float2*)&obase[(size_t)r0 * CDIM + dd] = o;
        }
        if (r1 < NSEQ) {
            float2 o; o.x = c_o[nt][2]; o.y = c_o[nt][3];
            *(float2*)&obase[(size_t)r1 * CDIM + dd] = o;
        }
    }
}

// ---------------------------------------------------------------------------
extern "C" void kernel_launch(void* const* d_in, const int* in_sizes, int n_in,
                              void* d_out, int out_size)
{
    const float* x          = (const float*)d_in[0];
    const float* mask       = (const float*)d_in[1];
    const float* qkv_w      = (const float*)d_in[2];
    const float* qkv_b      = (const float*)d_in[3];
    const float* proj_w     = (const float*)d_in[4];
    const float* proj_b     = (const float*)d_in[5];
    const float* bias_table = (const float*)d_in[6];
    float* out = (float*)d_out;

    float* qkv_ptr = nullptr;
    float* ao_ptr  = nullptr;
    cudaGetSymbolAddress((void**)&qkv_ptr, g_qkv);
    cudaGetSymbolAddress((void**)&ao_ptr, g_attnout);

    const int M = B_TOT * NSEQ;  // 100352

    {
        dim3 grid(THREECD / GBN, M / GBM);
        gemm_tf32_kernel<<<grid, 256>>>(x, qkv_w, qkv_b, qkv_ptr, M, CDIM, THREECD);
    }
    {
        dim3 grid(NHEADS, B_TOT);
        attn_mma_kernel<<<grid, 128>>>(qkv_ptr, mask, bias_table, ao_ptr);
    }
    {
        dim3 grid(CDIM / GBN, M / GBM);
        gemm_tf32_kernel<<<grid, 256>>>(ao_ptr, proj_w, proj_b, out, M, CDIM, CDIM);
    }
}

// round 4
// speedup vs baseline: 3.4445x; 1.1799x over previous
#include <cuda_runtime.h>
#include <cuda_bf16.h>
#include <math_constants.h>

// Problem constants
#define B_TOT   2048
#define NSEQ    49
#define CDIM    256
#define NHEADS  8
#define DHEAD   32
#define NW      64
#define THREECD 768

// Scratch (allocation-free rule: __device__ globals)
__device__ float g_qkv[(size_t)B_TOT * NSEQ * THREECD];     // [B, N, 3C]
__device__ float g_attnout[(size_t)B_TOT * NSEQ * CDIM];    // [B, N, C]
__device__ float g_comb[(size_t)NW * NHEADS * NSEQ * NSEQ]; // bias+mask combined

__device__ __forceinline__ float to_tf32(float x) {
    unsigned u = __float_as_uint(x);
    asm("cvt.rna.tf32.f32 %0, %1;" : "=r"(u) : "r"(u));
    return __uint_as_float(u);
}

__device__ __forceinline__ void mma_tf32(float (&c)[4], const unsigned (&a)[4],
                                         unsigned b0, unsigned b1) {
    asm volatile(
        "mma.sync.aligned.m16n8k8.row.col.f32.tf32.tf32.f32 "
        "{%0,%1,%2,%3}, {%4,%5,%6,%7}, {%8,%9}, {%0,%1,%2,%3};\n"
        : "+f"(c[0]), "+f"(c[1]), "+f"(c[2]), "+f"(c[3])
        : "r"(a[0]), "r"(a[1]), "r"(a[2]), "r"(a[3]), "r"(b0), "r"(b1));
}

__device__ __forceinline__ void ldsm4(unsigned (&r)[4], unsigned addr) {
    asm volatile("ldmatrix.sync.aligned.m8n8.x4.shared.b16 {%0,%1,%2,%3}, [%4];"
        : "=r"(r[0]), "=r"(r[1]), "=r"(r[2]), "=r"(r[3]) : "r"(addr));
}

// ---------------------------------------------------------------------------
// comb[w][h][i][j] = mask[w][i][j] + bias_table[rpi(i,j)][h]
// ---------------------------------------------------------------------------
__global__ void combine_kernel(const float* __restrict__ mask,
                               const float* __restrict__ bias_table,
                               float* __restrict__ comb)
{
    const int w = blockIdx.x, h = blockIdx.y;
    const float* mrow = mask + (size_t)w * NSEQ * NSEQ;
    float* crow = comb + ((size_t)w * NHEADS + h) * NSEQ * NSEQ;
    for (int p = threadIdx.x; p < NSEQ * NSEQ; p += blockDim.x) {
        int i = p / NSEQ, j = p - (p / NSEQ) * NSEQ;
        int i0 = i / 7, i1 = i - i0 * 7;
        int j0 = j / 7, j1 = j - j0 * 7;
        int ridx = (i0 - j0 + 6) * 13 + (i1 - j1 + 6);
        crow[p] = mrow[p] + bias_table[ridx * NHEADS + h];
    }
}

// ---------------------------------------------------------------------------
// TF32 tensor-core GEMM: C[M,N] = A[M,K] @ B[K,N] + bias[N]
// CTA 128x128, BK=16, 8 warps, warp tile 64x32 (2x4 warp grid).
// A-fragments via ldmatrix.x4; B via conflict-free scalar LDS.
// ---------------------------------------------------------------------------
#define GBM 128
#define GBN 128
#define GBK 16
#define ASTR 20
#define BSTR 136

__global__ __launch_bounds__(256, 2) void gemm_tf32_kernel(
    const float* __restrict__ A, const float* __restrict__ B,
    const float* __restrict__ bias, float* __restrict__ C,
    int M, int K, int N)
{
    __shared__ float As[2][GBM][ASTR];
    __shared__ float Bs[2][GBK][BSTR];

    const int tid  = threadIdx.x;
    const int wid  = tid >> 5;
    const int lane = tid & 31;
    const int wm   = wid & 1;       // 2 m-blocks of 64
    const int wn   = wid >> 1;      // 4 n-blocks of 32
    const int g    = lane >> 2;
    const int t    = lane & 3;
    const int rowC = blockIdx.y * GBM;
    const int colC = blockIdx.x * GBN;

    // ldmatrix lane addressing
    const int lrow  = (lane & 7) | (lane & 8);   // 0..15
    const int lcolA = (lane >> 4) << 2;          // 0 or 4

    const float* Aptr = A + (size_t)rowC * K;
    const float* Bptr = B + colC;

    const unsigned aBase = (unsigned)__cvta_generic_to_shared(
        &As[0][wm * 64 + lrow][lcolA]);
    const unsigned aBufStride = GBM * ASTR * 4;   // bytes per buffer
    const unsigned aMtStride  = 16 * ASTR * 4;    // 16 rows

    float acc[4][4][4];
#pragma unroll
    for (int mt = 0; mt < 4; mt++)
#pragma unroll
        for (int nt = 0; nt < 4; nt++)
#pragma unroll
            for (int r = 0; r < 4; r++) acc[mt][nt][r] = 0.f;

    float4 a_st[2], b_st[2];
    const int a_r0 = tid >> 2,         a_c0 = (tid & 3) * 4;
    const int a_r1 = (tid + 256) >> 2, a_c1 = ((tid + 256) & 3) * 4;
    const int b_r0 = tid >> 5,         b_c0 = (tid & 31) * 4;
    const int b_r1 = (tid + 256) >> 5, b_c1 = ((tid + 256) & 31) * 4;

    {
        a_st[0] = *(const float4*)(Aptr + (size_t)a_r0 * K + a_c0);
        a_st[1] = *(const float4*)(Aptr + (size_t)a_r1 * K + a_c1);
        b_st[0] = *(const float4*)(Bptr + (size_t)b_r0 * N + b_c0);
        b_st[1] = *(const float4*)(Bptr + (size_t)b_r1 * N + b_c1);
        float4 v;
        v.x = to_tf32(a_st[0].x); v.y = to_tf32(a_st[0].y);
        v.z = to_tf32(a_st[0].z); v.w = to_tf32(a_st[0].w);
        *(float4*)&As[0][a_r0][a_c0] = v;
        v.x = to_tf32(a_st[1].x); v.y = to_tf32(a_st[1].y);
        v.z = to_tf32(a_st[1].z); v.w = to_tf32(a_st[1].w);
        *(float4*)&As[0][a_r1][a_c1] = v;
        v.x = to_tf32(b_st[0].x); v.y = to_tf32(b_st[0].y);
        v.z = to_tf32(b_st[0].z); v.w = to_tf32(b_st[0].w);
        *(float4*)&Bs[0][b_r0][b_c0] = v;
        v.x = to_tf32(b_st[1].x); v.y = to_tf32(b_st[1].y);
        v.z = to_tf32(b_st[1].z); v.w = to_tf32(b_st[1].w);
        *(float4*)&Bs[0][b_r1][b_c1] = v;
    }
    __syncthreads();

    const int nk = K / GBK;
    int buf = 0;
    for (int kt = 0; kt < nk; kt++) {
        if (kt + 1 < nk) {
            const int k0 = (kt + 1) * GBK;
            a_st[0] = *(const float4*)(Aptr + (size_t)a_r0 * K + k0 + a_c0);
            a_st[1] = *(const float4*)(Aptr + (size_t)a_r1 * K + k0 + a_c1);
            b_st[0] = *(const float4*)(Bptr + (size_t)(k0 + b_r0) * N + b_c0);
            b_st[1] = *(const float4*)(Bptr + (size_t)(k0 + b_r1) * N + b_c1);
        }

        const unsigned aBuf = aBase + (unsigned)buf * aBufStride;
#pragma unroll
        for (int s = 0; s < 2; s++) {
            const int k8 = s * 8;
            unsigned af[4][4];
#pragma unroll
            for (int mt = 0; mt < 4; mt++)
                ldsm4(af[mt], aBuf + mt * aMtStride + k8 * 4);
#pragma unroll
            for (int nt = 0; nt < 4; nt++) {
                const int col = wn * 32 + nt * 8 + g;
                unsigned b0 = __float_as_uint(Bs[buf][k8 + t][col]);
                unsigned b1 = __float_as_uint(Bs[buf][k8 + t + 4][col]);
#pragma unroll
                for (int mt = 0; mt < 4; mt++)
                    mma_tf32(acc[mt][nt], af[mt], b0, b1);
            }
        }

        if (kt + 1 < nk) {
            const int nb = buf ^ 1;
            float4 v;
            v.x = to_tf32(a_st[0].x); v.y = to_tf32(a_st[0].y);
            v.z = to_tf32(a_st[0].z); v.w = to_tf32(a_st[0].w);
            *(float4*)&As[nb][a_r0][a_c0] = v;
            v.x = to_tf32(a_st[1].x); v.y = to_tf32(a_st[1].y);
            v.z = to_tf32(a_st[1].z); v.w = to_tf32(a_st[1].w);
            *(float4*)&As[nb][a_r1][a_c1] = v;
            v.x = to_tf32(b_st[0].x); v.y = to_tf32(b_st[0].y);
            v.z = to_tf32(b_st[0].z); v.w = to_tf32(b_st[0].w);
            *(float4*)&Bs[nb][b_r0][b_c0] = v;
            v.x = to_tf32(b_st[1].x); v.y = to_tf32(b_st[1].y);
            v.z = to_tf32(b_st[1].z); v.w = to_tf32(b_st[1].w);
            *(float4*)&Bs[nb][b_r1][b_c1] = v;
            __syncthreads();
            buf = nb;
        }
    }

#pragma unroll
    for (int mt = 0; mt < 4; mt++) {
        const int r0 = rowC + wm * 64 + mt * 16 + g;
#pragma unroll
        for (int nt = 0; nt < 4; nt++) {
            const int cc = colC + wn * 32 + nt * 8 + 2 * t;
            const float bb0 = bias[cc], bb1 = bias[cc + 1];
            float2 o;
            o.x = acc[mt][nt][0] + bb0;
            o.y = acc[mt][nt][1] + bb1;
            *(float2*)&C[(size_t)r0 * N + cc] = o;
            o.x = acc[mt][nt][2] + bb0;
            o.y = acc[mt][nt][3] + bb1;
            *(float2*)&C[(size_t)(r0 + 8) * N + cc] = o;
        }
    }
}

// ---------------------------------------------------------------------------
// Tensor-core window attention v2: one CTA per (b, h), 4 warps.
// Warp-local softmax (no cross-warp sync after load), ldmatrix fragments.
// ---------------------------------------------------------------------------
__global__ __launch_bounds__(128) void attn_mma_kernel(
    const float* __restrict__ qkv, const float* __restrict__ comb,
    float* __restrict__ out)
{
    const int h = blockIdx.x;
    const int b = blockIdx.y;

    __shared__ float qs[64][36];
    __shared__ float ks[56][36];
    __shared__ float vs[56][40];
    __shared__ float sc[64][68];

    const int tid   = threadIdx.x;
    const int lane  = tid & 31;
    const int wid   = tid >> 5;
    const int g     = lane >> 2;
    const int t     = lane & 3;
    const int lrow  = (lane & 7) | (lane & 8);
    const int lcolA = (lane >> 4) << 2;
    const float scale = 0.17677669529663687f;

    const float* base = qkv + (size_t)b * NSEQ * THREECD + h * DHEAD;
    for (int f = tid; f < NSEQ * 8; f += 128) {
        int n = f >> 3, c = (f & 7) << 2;
        const float* row = base + (size_t)n * THREECD;
        float4 q4 = *(const float4*)(row + c);
        float4 k4 = *(const float4*)(row + CDIM + c);
        float4 v4 = *(const float4*)(row + 2 * CDIM + c);
        float4 o;
        o.x = to_tf32(q4.x * scale); o.y = to_tf32(q4.y * scale);
        o.z = to_tf32(q4.z * scale); o.w = to_tf32(q4.w * scale);
        *(float4*)&qs[n][c] = o;
        o.x = to_tf32(k4.x); o.y = to_tf32(k4.y);
        o.z = to_tf32(k4.z); o.w = to_tf32(k4.w);
        *(float4*)&ks[n][c] = o;
        o.x = to_tf32(v4.x); o.y = to_tf32(v4.y);
        o.z = to_tf32(v4.z); o.w = to_tf32(v4.w);
        *(float4*)&vs[n][c] = o;
    }
    for (int z = tid; z < 7 * 40; z += 128) vs[NSEQ + z / 40][z % 40] = 0.f;
    __syncthreads();

    const int row = wid * 16;

    // ---- QK^T
    float c_sc[7][4];
#pragma unroll
    for (int nt = 0; nt < 7; nt++)
#pragma unroll
        for (int r = 0; r < 4; r++) c_sc[nt][r] = 0.f;

    const unsigned qAddr = (unsigned)__cvta_generic_to_shared(
        &qs[row + lrow][lcolA]);
#pragma unroll
    for (int kk = 0; kk < 4; kk++) {
        const int k8 = kk * 8;
        unsigned a[4];
        ldsm4(a, qAddr + kk * 32);
#pragma unroll
        for (int nt = 0; nt < 7; nt++) {
            unsigned b0 = __float_as_uint(ks[nt * 8 + g][k8 + t]);
            unsigned b1 = __float_as_uint(ks[nt * 8 + g][k8 + t + 4]);
            mma_tf32(c_sc[nt], a, b0, b1);
        }
    }

    // ---- epilogue + warp-local softmax (rows r0, r1 fully in-warp)
    const int r0 = row + g, r1 = r0 + 8;
    const float* cb = comb + ((size_t)(b & (NW - 1)) * NHEADS + h) * NSEQ * NSEQ;

    float mx0 = -CUDART_INF_F, mx1 = -CUDART_INF_F;
#pragma unroll
    for (int nt = 0; nt < 7; nt++) {
#pragma unroll
        for (int cx = 0; cx < 2; cx++) {
            const int cc = nt * 8 + 2 * t + cx;
            float v0 = (r0 < NSEQ && cc < NSEQ)
                     ? c_sc[nt][cx] + cb[r0 * NSEQ + cc] : -CUDART_INF_F;
            float v1 = (r1 < NSEQ && cc < NSEQ)
                     ? c_sc[nt][2 + cx] + cb[r1 * NSEQ + cc] : -CUDART_INF_F;
            c_sc[nt][cx] = v0;     mx0 = fmaxf(mx0, v0);
            c_sc[nt][2 + cx] = v1; mx1 = fmaxf(mx1, v1);
        }
    }
    // quad allreduce (cols of a row live in lanes 4g..4g+3)
    mx0 = fmaxf(mx0, __shfl_xor_sync(0xffffffffu, mx0, 1));
    mx0 = fmaxf(mx0, __shfl_xor_sync(0xffffffffu, mx0, 2));
    mx1 = fmaxf(mx1, __shfl_xor_sync(0xffffffffu, mx1, 1));
    mx1 = fmaxf(mx1, __shfl_xor_sync(0xffffffffu, mx1, 2));

    float s0 = 0.f, s1 = 0.f;
#pragma unroll
    for (int nt = 0; nt < 7; nt++) {
#pragma unroll
        for (int cx = 0; cx < 2; cx++) {
            float e0 = __expf(c_sc[nt][cx] - mx0);
            float e1 = __expf(c_sc[nt][2 + cx] - mx1);
            c_sc[nt][cx] = e0;     s0 += e0;
            c_sc[nt][2 + cx] = e1; s1 += e1;
        }
    }
    s0 += __shfl_xor_sync(0xffffffffu, s0, 1);
    s0 += __shfl_xor_sync(0xffffffffu, s0, 2);
    s1 += __shfl_xor_sync(0xffffffffu, s1, 1);
    s1 += __shfl_xor_sync(0xffffffffu, s1, 2);
    const float inv0 = 1.f / s0, inv1 = 1.f / s1;

#pragma unroll
    for (int nt = 0; nt < 7; nt++) {
        float2 p;
        p.x = c_sc[nt][0] * inv0; p.y = c_sc[nt][1] * inv0;
        *(float2*)&sc[r0][nt * 8 + 2 * t] = p;
        p.x = c_sc[nt][2] * inv1; p.y = c_sc[nt][3] * inv1;
        *(float2*)&sc[r1][nt * 8 + 2 * t] = p;
    }
    __syncwarp();

    // ---- AV (split-tf32 on P)
    float c_o[4][4];
#pragma unroll
    for (int nt = 0; nt < 4; nt++)
#pragma unroll
        for (int r = 0; r < 4; r++) c_o[nt][r] = 0.f;

    const unsigned pAddr = (unsigned)__cvta_generic_to_shared(
        &sc[row + lrow][lcolA]);
#pragma unroll
    for (int kk = 0; kk < 7; kk++) {
        const int k8 = kk * 8;
        unsigned praw[4];
        ldsm4(praw, pAddr + kk * 32);
        unsigned ah[4], al[4];
#pragma unroll
        for (int r = 0; r < 4; r++) {
            float f = __uint_as_float(praw[r]);
            float hi = to_tf32(f);
            ah[r] = __float_as_uint(hi);
            al[r] = __float_as_uint(to_tf32(f - hi));
        }
#pragma unroll
        for (int nt = 0; nt < 4; nt++) {
            unsigned b0 = __float_as_uint(vs[k8 + t][nt * 8 + g]);
            unsigned b1 = __float_as_uint(vs[k8 + t + 4][nt * 8 + g]);
            mma_tf32(c_o[nt], ah, b0, b1);
            mma_tf32(c_o[nt], al, b0, b1);
        }
    }

    float* obase = out + (size_t)b * NSEQ * CDIM + h * DHEAD;
#pragma unroll
    for (int nt = 0; nt < 4; nt++) {
        const int dd = nt * 8 + 2 * t;
        if (r0 < NSEQ) {
            float2 o; o.x = c_o[nt][0]; o.y = c_o[nt][1];
            *(float2*)&obase[(size_t)r0 * CDIM + dd] = o;
        }
        if (r1 < NSEQ) {
            float2 o; o.x = c_o[nt][2]; o.y = c_o[nt][3];
            *(float2*)&obase[(size_t)r1 * CDIM + dd] = o;
        }
    }
}

// ---------------------------------------------------------------------------
extern "C" void kernel_launch(void* const* d_in, const int* in_sizes, int n_in,
                              void* d_out, int out_size)
{
    const float* x          = (const float*)d_in[0];
    const float* mask       = (const float*)d_in[1];
    const float* qkv_w      = (const float*)d_in[2];
    const float* qkv_b      = (const float*)d_in[3];
    const float* proj_w     = (const float*)d_in[4];
    const float* proj_b     = (const float*)d_in[5];
    const float* bias_table = (const float*)d_in[6];
    float* out = (float*)d_out;

    float* qkv_ptr = nullptr;
    float* ao_ptr  = nullptr;
    float* comb_ptr = nullptr;
    cudaGetSymbolAddress((void**)&qkv_ptr, g_qkv);
    cudaGetSymbolAddress((void**)&ao_ptr, g_attnout);
    cudaGetSymbolAddress((void**)&comb_ptr, g_comb);

    const int M = B_TOT * NSEQ;  // 100352

    {
        dim3 grid(NW, NHEADS);
        combine_kernel<<<grid, 128>>>(mask, bias_table, comb_ptr);
    }
    {
        dim3 grid(THREECD / GBN, M / GBM);
        gemm_tf32_kernel<<<grid, 256>>>(x, qkv_w, qkv_b, qkv_ptr, M, CDIM, THREECD);
    }
    {
        dim3 grid(NHEADS, B_TOT);
        attn_mma_kernel<<<grid, 128>>>(qkv_ptr, comb_ptr, ao_ptr);
    }
    {
        dim3 grid(CDIM / GBN, M / GBM);
        gemm_tf32_kernel<<<grid, 256>>>(ao_ptr, proj_w, proj_b, out, M, CDIM, CDIM);
    }
}

// round 5
// speedup vs baseline: 3.6198x; 1.0509x over previous
#include <cuda_runtime.h>
#include <cuda_bf16.h>
#include <math_constants.h>

// Problem constants
#define B_TOT   2048
#define NSEQ    49
#define CDIM    256
#define NHEADS  8
#define DHEAD   32
#define NW      64
#define THREECD 768

// Scratch (allocation-free rule: __device__ globals)
__device__ float g_qkv[(size_t)B_TOT * NSEQ * THREECD];     // [B, N, 3C]
__device__ float g_attnout[(size_t)B_TOT * NSEQ * CDIM];    // [B, N, C]
__device__ float g_comb[(size_t)NW * NHEADS * NSEQ * NSEQ]; // bias+mask combined

__device__ __forceinline__ float to_tf32(float x) {
    unsigned u = __float_as_uint(x);
    asm("cvt.rna.tf32.f32 %0, %1;" : "=r"(u) : "r"(u));
    return __uint_as_float(u);
}

__device__ __forceinline__ unsigned cvt_tf32_bits(unsigned u) {
    asm("cvt.rna.tf32.f32 %0, %1;" : "=r"(u) : "r"(u));
    return u;
}

__device__ __forceinline__ void mma_tf32(float (&c)[4], const unsigned (&a)[4],
                                         unsigned b0, unsigned b1) {
    asm volatile(
        "mma.sync.aligned.m16n8k8.row.col.f32.tf32.tf32.f32 "
        "{%0,%1,%2,%3}, {%4,%5,%6,%7}, {%8,%9}, {%0,%1,%2,%3};\n"
        : "+f"(c[0]), "+f"(c[1]), "+f"(c[2]), "+f"(c[3])
        : "r"(a[0]), "r"(a[1]), "r"(a[2]), "r"(a[3]), "r"(b0), "r"(b1));
}

__device__ __forceinline__ void ldsm4(unsigned (&r)[4], unsigned addr) {
    asm volatile("ldmatrix.sync.aligned.m8n8.x4.shared.b16 {%0,%1,%2,%3}, [%4];"
        : "=r"(r[0]), "=r"(r[1]), "=r"(r[2]), "=r"(r[3]) : "r"(addr));
}

__device__ __forceinline__ void cp_async16(unsigned smem_addr, const void* gptr) {
    asm volatile("cp.async.cg.shared.global [%0], [%1], 16;"
                 :: "r"(smem_addr), "l"(gptr));
}
__device__ __forceinline__ void cp_commit() {
    asm volatile("cp.async.commit_group;");
}
__device__ __forceinline__ void cp_wait0() {
    asm volatile("cp.async.wait_group 0;");
}

// ---------------------------------------------------------------------------
// comb[w][h][i][j] = mask[w][i][j] + bias_table[rpi(i,j)][h]
// ---------------------------------------------------------------------------
__global__ void combine_kernel(const float* __restrict__ mask,
                               const float* __restrict__ bias_table,
                               float* __restrict__ comb)
{
    const int w = blockIdx.x, h = blockIdx.y;
    const float* mrow = mask + (size_t)w * NSEQ * NSEQ;
    float* crow = comb + ((size_t)w * NHEADS + h) * NSEQ * NSEQ;
    for (int p = threadIdx.x; p < NSEQ * NSEQ; p += blockDim.x) {
        int i = p / NSEQ, j = p - (p / NSEQ) * NSEQ;
        int i0 = i / 7, i1 = i - i0 * 7;
        int j0 = j / 7, j1 = j - j0 * 7;
        int ridx = (i0 - j0 + 6) * 13 + (i1 - j1 + 6);
        crow[p] = mrow[p] + bias_table[ridx * NHEADS + h];
    }
}

// ---------------------------------------------------------------------------
// TF32 tensor-core GEMM v3: C[M,N] = A[M,K] @ B[K,N] + bias[N]
// CTA 128x128, BK=16, 8 warps, warp tile 64x32 (2x4).
// cp.async.cg double-buffered loads (no staging, no STS); RNA cvt on fragments.
// ---------------------------------------------------------------------------
#define GBM 128
#define GBN 128
#define GBK 16
#define ASTR 20
#define BSTR 136
#define ABUF (GBM * ASTR * 4)   // bytes per A stage
#define BBUF (GBK * BSTR * 4)   // bytes per B stage

__global__ __launch_bounds__(256, 2) void gemm_tf32_kernel(
    const float* __restrict__ A, const float* __restrict__ B,
    const float* __restrict__ bias, float* __restrict__ C,
    int M, int K, int N)
{
    __shared__ float As[2][GBM][ASTR];
    __shared__ float Bs[2][GBK][BSTR];

    const int tid  = threadIdx.x;
    const int wid  = tid >> 5;
    const int lane = tid & 31;
    const int wm   = wid & 1;       // 2 m-blocks of 64
    const int wn   = wid >> 1;      // 4 n-blocks of 32
    const int g    = lane >> 2;
    const int t    = lane & 3;
    const int rowC = blockIdx.y * GBM;
    const int colC = blockIdx.x * GBN;

    const int lrow  = (lane & 7) | (lane & 8);
    const int lcolA = (lane >> 4) << 2;

    const float* Aptr = A + (size_t)rowC * K;
    const float* Bptr = B + colC;

    // cp.async loader mapping
    const int a_r0 = tid >> 2,         a_c0 = (tid & 3) * 4;
    const int a_r1 = (tid + 256) >> 2, a_c1 = ((tid + 256) & 3) * 4;
    const int b_r0 = tid >> 5,         b_c0 = (tid & 31) * 4;
    const int b_r1 = (tid + 256) >> 5, b_c1 = ((tid + 256) & 31) * 4;

    const unsigned asBase = (unsigned)__cvta_generic_to_shared(&As[0][0][0]);
    const unsigned bsBase = (unsigned)__cvta_generic_to_shared(&Bs[0][0][0]);
    const unsigned aOff0 = (unsigned)(a_r0 * ASTR + a_c0) * 4;
    const unsigned aOff1 = (unsigned)(a_r1 * ASTR + a_c1) * 4;
    const unsigned bOff0 = (unsigned)(b_r0 * BSTR + b_c0) * 4;
    const unsigned bOff1 = (unsigned)(b_r1 * BSTR + b_c1) * 4;

    const unsigned aFragBase = (unsigned)__cvta_generic_to_shared(
        &As[0][wm * 64 + lrow][lcolA]);

    float acc[4][4][4];
#pragma unroll
    for (int mt = 0; mt < 4; mt++)
#pragma unroll
        for (int nt = 0; nt < 4; nt++)
#pragma unroll
            for (int r = 0; r < 4; r++) acc[mt][nt][r] = 0.f;

    // ---- prologue: async-load stage 0
    cp_async16(asBase + aOff0, Aptr + (size_t)a_r0 * K + a_c0);
    cp_async16(asBase + aOff1, Aptr + (size_t)a_r1 * K + a_c1);
    cp_async16(bsBase + bOff0, Bptr + (size_t)b_r0 * N + b_c0);
    cp_async16(bsBase + bOff1, Bptr + (size_t)b_r1 * N + b_c1);
    cp_commit();
    cp_wait0();
    __syncthreads();

    const int nk = K / GBK;
    int buf = 0;
    for (int kt = 0; kt < nk; kt++) {
        // issue next stage first so the copy overlaps this tile's MMA work
        if (kt + 1 < nk) {
            const int k0 = (kt + 1) * GBK;
            const unsigned sb = (unsigned)(buf ^ 1);
            cp_async16(asBase + sb * ABUF + aOff0, Aptr + (size_t)a_r0 * K + k0 + a_c0);
            cp_async16(asBase + sb * ABUF + aOff1, Aptr + (size_t)a_r1 * K + k0 + a_c1);
            cp_async16(bsBase + sb * BBUF + bOff0, Bptr + (size_t)(k0 + b_r0) * N + b_c0);
            cp_async16(bsBase + sb * BBUF + bOff1, Bptr + (size_t)(k0 + b_r1) * N + b_c1);
            cp_commit();
        }

        const unsigned aBuf = aFragBase + (unsigned)buf * ABUF;
#pragma unroll
        for (int s = 0; s < 2; s++) {
            const int k8 = s * 8;
            unsigned af[4][4];
#pragma unroll
            for (int mt = 0; mt < 4; mt++) {
                ldsm4(af[mt], aBuf + mt * (16 * ASTR * 4) + k8 * 4);
#pragma unroll
                for (int r = 0; r < 4; r++) af[mt][r] = cvt_tf32_bits(af[mt][r]);
            }
#pragma unroll
            for (int nt = 0; nt < 4; nt++) {
                const int col = wn * 32 + nt * 8 + g;
                unsigned b0 = cvt_tf32_bits(__float_as_uint(Bs[buf][k8 + t][col]));
                unsigned b1 = cvt_tf32_bits(__float_as_uint(Bs[buf][k8 + t + 4][col]));
#pragma unroll
                for (int mt = 0; mt < 4; mt++)
                    mma_tf32(acc[mt][nt], af[mt], b0, b1);
            }
        }

        if (kt + 1 < nk) {
            cp_wait0();
            __syncthreads();
            buf ^= 1;
        }
    }

#pragma unroll
    for (int mt = 0; mt < 4; mt++) {
        const int r0 = rowC + wm * 64 + mt * 16 + g;
#pragma unroll
        for (int nt = 0; nt < 4; nt++) {
            const int cc = colC + wn * 32 + nt * 8 + 2 * t;
            const float bb0 = bias[cc], bb1 = bias[cc + 1];
            float2 o;
            o.x = acc[mt][nt][0] + bb0;
            o.y = acc[mt][nt][1] + bb1;
            *(float2*)&C[(size_t)r0 * N + cc] = o;
            o.x = acc[mt][nt][2] + bb0;
            o.y = acc[mt][nt][3] + bb1;
            *(float2*)&C[(size_t)(r0 + 8) * N + cc] = o;
        }
    }
}

// ---------------------------------------------------------------------------
// Tensor-core window attention: one CTA per (b, h), 4 warps.
// Warp-local softmax, ldmatrix fragments. (unchanged from round 4)
// ---------------------------------------------------------------------------
__global__ __launch_bounds__(128) void attn_mma_kernel(
    const float* __restrict__ qkv, const float* __restrict__ comb,
    float* __restrict__ out)
{
    const int h = blockIdx.x;
    const int b = blockIdx.y;

    __shared__ float qs[64][36];
    __shared__ float ks[56][36];
    __shared__ float vs[56][40];
    __shared__ float sc[64][68];

    const int tid   = threadIdx.x;
    const int lane  = tid & 31;
    const int wid   = tid >> 5;
    const int g     = lane >> 2;
    const int t     = lane & 3;
    const int lrow  = (lane & 7) | (lane & 8);
    const int lcolA = (lane >> 4) << 2;
    const float scale = 0.17677669529663687f;

    const float* base = qkv + (size_t)b * NSEQ * THREECD + h * DHEAD;
    for (int f = tid; f < NSEQ * 8; f += 128) {
        int n = f >> 3, c = (f & 7) << 2;
        const float* row = base + (size_t)n * THREECD;
        float4 q4 = *(const float4*)(row + c);
        float4 k4 = *(const float4*)(row + CDIM + c);
        float4 v4 = *(const float4*)(row + 2 * CDIM + c);
        float4 o;
        o.x = to_tf32(q4.x * scale); o.y = to_tf32(q4.y * scale);
        o.z = to_tf32(q4.z * scale); o.w = to_tf32(q4.w * scale);
        *(float4*)&qs[n][c] = o;
        o.x = to_tf32(k4.x); o.y = to_tf32(k4.y);
        o.z = to_tf32(k4.z); o.w = to_tf32(k4.w);
        *(float4*)&ks[n][c] = o;
        o.x = to_tf32(v4.x); o.y = to_tf32(v4.y);
        o.z = to_tf32(v4.z); o.w = to_tf32(v4.w);
        *(float4*)&vs[n][c] = o;
    }
    for (int z = tid; z < 7 * 40; z += 128) vs[NSEQ + z / 40][z % 40] = 0.f;
    __syncthreads();

    const int row = wid * 16;

    // ---- QK^T
    float c_sc[7][4];
#pragma unroll
    for (int nt = 0; nt < 7; nt++)
#pragma unroll
        for (int r = 0; r < 4; r++) c_sc[nt][r] = 0.f;

    const unsigned qAddr = (unsigned)__cvta_generic_to_shared(
        &qs[row + lrow][lcolA]);
#pragma unroll
    for (int kk = 0; kk < 4; kk++) {
        const int k8 = kk * 8;
        unsigned a[4];
        ldsm4(a, qAddr + kk * 32);
#pragma unroll
        for (int nt = 0; nt < 7; nt++) {
            unsigned b0 = __float_as_uint(ks[nt * 8 + g][k8 + t]);
            unsigned b1 = __float_as_uint(ks[nt * 8 + g][k8 + t + 4]);
            mma_tf32(c_sc[nt], a, b0, b1);
        }
    }

    // ---- epilogue + warp-local softmax
    const int r0 = row + g, r1 = r0 + 8;
    const float* cb = comb + ((size_t)(b & (NW - 1)) * NHEADS + h) * NSEQ * NSEQ;

    float mx0 = -CUDART_INF_F, mx1 = -CUDART_INF_F;
#pragma unroll
    for (int nt = 0; nt < 7; nt++) {
#pragma unroll
        for (int cx = 0; cx < 2; cx++) {
            const int cc = nt * 8 + 2 * t + cx;
            float v0 = (r0 < NSEQ && cc < NSEQ)
                     ? c_sc[nt][cx] + cb[r0 * NSEQ + cc] : -CUDART_INF_F;
            float v1 = (r1 < NSEQ && cc < NSEQ)
                     ? c_sc[nt][2 + cx] + cb[r1 * NSEQ + cc] : -CUDART_INF_F;
            c_sc[nt][cx] = v0;     mx0 = fmaxf(mx0, v0);
            c_sc[nt][2 + cx] = v1; mx1 = fmaxf(mx1, v1);
        }
    }
    mx0 = fmaxf(mx0, __shfl_xor_sync(0xffffffffu, mx0, 1));
    mx0 = fmaxf(mx0, __shfl_xor_sync(0xffffffffu, mx0, 2));
    mx1 = fmaxf(mx1, __shfl_xor_sync(0xffffffffu, mx1, 1));
    mx1 = fmaxf(mx1, __shfl_xor_sync(0xffffffffu, mx1, 2));

    float s0 = 0.f, s1 = 0.f;
#pragma unroll
    for (int nt = 0; nt < 7; nt++) {
#pragma unroll
        for (int cx = 0; cx < 2; cx++) {
            float e0 = __expf(c_sc[nt][cx] - mx0);
            float e1 = __expf(c_sc[nt][2 + cx] - mx1);
            c_sc[nt][cx] = e0;     s0 += e0;
            c_sc[nt][2 + cx] = e1; s1 += e1;
        }
    }
    s0 += __shfl_xor_sync(0xffffffffu, s0, 1);
    s0 += __shfl_xor_sync(0xffffffffu, s0, 2);
    s1 += __shfl_xor_sync(0xffffffffu, s1, 1);
    s1 += __shfl_xor_sync(0xffffffffu, s1, 2);
    const float inv0 = 1.f / s0, inv1 = 1.f / s1;

#pragma unroll
    for (int nt = 0; nt < 7; nt++) {
        float2 p;
        p.x = c_sc[nt][0] * inv0; p.y = c_sc[nt][1] * inv0;
        *(float2*)&sc[r0][nt * 8 + 2 * t] = p;
        p.x = c_sc[nt][2] * inv1; p.y = c_sc[nt][3] * inv1;
        *(float2*)&sc[r1][nt * 8 + 2 * t] = p;
    }
    __syncwarp();

    // ---- AV (split-tf32 on P)
    float c_o[4][4];
#pragma unroll
    for (int nt = 0; nt < 4; nt++)
#pragma unroll
        for (int r = 0; r < 4; r++) c_o[nt][r] = 0.f;

    const unsigned pAddr = (unsigned)__cvta_generic_to_shared(
        &sc[row + lrow][lcolA]);
#pragma unroll
    for (int kk = 0; kk < 7; kk++) {
        const int k8 = kk * 8;
        unsigned praw[4];
        ldsm4(praw, pAddr + kk * 32);
        unsigned ah[4], al[4];
#pragma unroll
        for (int r = 0; r < 4; r++) {
            float f = __uint_as_float(praw[r]);
            float hi = to_tf32(f);
            ah[r] = __float_as_uint(hi);
            al[r] = __float_as_uint(to_tf32(f - hi));
        }
#pragma unroll
        for (int nt = 0; nt < 4; nt++) {
            unsigned b0 = __float_as_uint(vs[k8 + t][nt * 8 + g]);
            unsigned b1 = __float_as_uint(vs[k8 + t + 4][nt * 8 + g]);
            mma_tf32(c_o[nt], ah, b0, b1);
            mma_tf32(c_o[nt], al, b0, b1);
        }
    }

    float* obase = out + (size_t)b * NSEQ * CDIM + h * DHEAD;
#pragma unroll
    for (int nt = 0; nt < 4; nt++) {
        const int dd = nt * 8 + 2 * t;
        if (r0 < NSEQ) {
            float2 o; o.x = c_o[nt][0]; o.y = c_o[nt][1];
            *(float2*)&obase[(size_t)r0 * CDIM + dd] = o;
        }
        if (r1 < NSEQ) {
            float2 o; o.x = c_o[nt][2]; o.y = c_o[nt][3];
            *(float2*)&obase[(size_t)r1 * CDIM + dd] = o;
        }
    }
}

// ---------------------------------------------------------------------------
extern "C" void kernel_launch(void* const* d_in, const int* in_sizes, int n_in,
                              void* d_out, int out_size)
{
    const float* x          = (const float*)d_in[0];
    const float* mask       = (const float*)d_in[1];
    const float* qkv_w      = (const float*)d_in[2];
    const float* qkv_b      = (const float*)d_in[3];
    const float* proj_w     = (const float*)d_in[4];
    const float* proj_b     = (const float*)d_in[5];
    const float* bias_table = (const float*)d_in[6];
    float* out = (float*)d_out;

    float* qkv_ptr = nullptr;
    float* ao_ptr  = nullptr;
    float* comb_ptr = nullptr;
    cudaGetSymbolAddress((void**)&qkv_ptr, g_qkv);
    cudaGetSymbolAddress((void**)&ao_ptr, g_attnout);
    cudaGetSymbolAddress((void**)&comb_ptr, g_comb);

    const int M = B_TOT * NSEQ;  // 100352

    {
        dim3 grid(NW, NHEADS);
        combine_kernel<<<grid, 128>>>(mask, bias_table, comb_ptr);
    }
    {
        dim3 grid(THREECD / GBN, M / GBM);
        gemm_tf32_kernel<<<grid, 256>>>(x, qkv_w, qkv_b, qkv_ptr, M, CDIM, THREECD);
    }
    {
        dim3 grid(NHEADS, B_TOT);
        attn_mma_kernel<<<grid, 128>>>(qkv_ptr, comb_ptr, ao_ptr);
    }
    {
        dim3 grid(CDIM / GBN, M / GBM);
        gemm_tf32_kernel<<<grid, 256>>>(ao_ptr, proj_w, proj_b, out, M, CDIM, CDIM);
    }
}

// round 6
// speedup vs baseline: 3.7986x; 1.0494x over previous
#include <cuda_runtime.h>
#include <cuda_bf16.h>
#include <math_constants.h>

// Problem constants
#define B_TOT   2048
#define NSEQ    49
#define CDIM    256
#define NHEADS  8
#define DHEAD   32
#define NW      64
#define THREECD 768

// Scratch (allocation-free rule: __device__ globals)
__device__ float g_qkv[(size_t)B_TOT * NSEQ * THREECD];     // [B, N, 3C]
__device__ float g_attnout[(size_t)B_TOT * NSEQ * CDIM];    // [B, N, C] (tf32-rounded)
__device__ float g_comb[(size_t)NW * NHEADS * NSEQ * NSEQ]; // bias+mask combined
__device__ float g_xr[(size_t)B_TOT * NSEQ * CDIM];         // x, tf32-rounded
__device__ float g_wqkv[(size_t)CDIM * THREECD];            // qkv_w, tf32-rounded
__device__ float g_wproj[(size_t)CDIM * CDIM];              // proj_w, tf32-rounded

__device__ __forceinline__ float to_tf32(float x) {
    unsigned u = __float_as_uint(x);
    asm("cvt.rna.tf32.f32 %0, %1;" : "=r"(u) : "r"(u));
    return __uint_as_float(u);
}

__device__ __forceinline__ void mma_tf32(float (&c)[4], const unsigned (&a)[4],
                                         unsigned b0, unsigned b1) {
    asm volatile(
        "mma.sync.aligned.m16n8k8.row.col.f32.tf32.tf32.f32 "
        "{%0,%1,%2,%3}, {%4,%5,%6,%7}, {%8,%9}, {%0,%1,%2,%3};\n"
        : "+f"(c[0]), "+f"(c[1]), "+f"(c[2]), "+f"(c[3])
        : "r"(a[0]), "r"(a[1]), "r"(a[2]), "r"(a[3]), "r"(b0), "r"(b1));
}

__device__ __forceinline__ void ldsm4(unsigned (&r)[4], unsigned addr) {
    asm volatile("ldmatrix.sync.aligned.m8n8.x4.shared.b16 {%0,%1,%2,%3}, [%4];"
        : "=r"(r[0]), "=r"(r[1]), "=r"(r[2]), "=r"(r[3]) : "r"(addr));
}

__device__ __forceinline__ void cp_async16(unsigned smem_addr, const void* gptr) {
    asm volatile("cp.async.cg.shared.global [%0], [%1], 16;"
                 :: "r"(smem_addr), "l"(gptr));
}
__device__ __forceinline__ void cp_commit() {
    asm volatile("cp.async.commit_group;");
}

// ---------------------------------------------------------------------------
// tf32 pre-round pass (float4 grid-stride)
// ---------------------------------------------------------------------------
__global__ void round_tf32_kernel(const float4* __restrict__ src,
                                  float4* __restrict__ dst, int n4)
{
    int i = blockIdx.x * blockDim.x + threadIdx.x;
    if (i < n4) {
        float4 v = src[i];
        v.x = to_tf32(v.x); v.y = to_tf32(v.y);
        v.z = to_tf32(v.z); v.w = to_tf32(v.w);
        dst[i] = v;
    }
}

// ---------------------------------------------------------------------------
// comb[w][h][i][j] = mask[w][i][j] + bias_table[rpi(i,j)][h]
// ---------------------------------------------------------------------------
__global__ void combine_kernel(const float* __restrict__ mask,
                               const float* __restrict__ bias_table,
                               float* __restrict__ comb)
{
    const int w = blockIdx.x, h = blockIdx.y;
    const float* mrow = mask + (size_t)w * NSEQ * NSEQ;
    float* crow = comb + ((size_t)w * NHEADS + h) * NSEQ * NSEQ;
    for (int p = threadIdx.x; p < NSEQ * NSEQ; p += blockDim.x) {
        int i = p / NSEQ, j = p - (p / NSEQ) * NSEQ;
        int i0 = i / 7, i1 = i - i0 * 7;
        int j0 = j / 7, j1 = j - j0 * 7;
        int ridx = (i0 - j0 + 6) * 13 + (i1 - j1 + 6);
        crow[p] = mrow[p] + bias_table[ridx * NHEADS + h];
    }
}

// ---------------------------------------------------------------------------
// TF32 tensor-core GEMM v4: C[M,N] = A[M,K] @ B[K,N] + bias[N]
// CTA 128x128, BK=16, 8 warps (2m x 4n), warp tile 64x32.
// 4-stage cp.async pipeline, pre-rounded inputs (no in-loop cvt).
// ---------------------------------------------------------------------------
#define GBM 128
#define GBN 128
#define GBK 16
#define ASTR 20
#define BSTR 136
#define STAGES 4
#define ABUF (GBM * ASTR * 4)         // 10240 B per A stage
#define BBUF (GBK * BSTR * 4)         // 8704 B per B stage
#define ASTAGE_F (GBM * ASTR)         // 2560 floats
#define BSTAGE_F (GBK * BSTR)         // 2176 floats
#define GEMM_SMEM (STAGES * (ABUF + BBUF))   // 75776 B

__global__ __launch_bounds__(256, 2) void gemm_tf32_kernel(
    const float* __restrict__ A, const float* __restrict__ B,
    const float* __restrict__ bias, float* __restrict__ C,
    int M, int K, int N)
{
    extern __shared__ float sm[];
    float* AsF = sm;                          // STAGES * ASTAGE_F
    float* BsF = sm + STAGES * ASTAGE_F;      // STAGES * BSTAGE_F

    const int tid  = threadIdx.x;
    const int wid  = tid >> 5;
    const int lane = tid & 31;
    const int wm   = wid & 1;
    const int wn   = wid >> 1;
    const int g    = lane >> 2;
    const int t    = lane & 3;
    const int rowC = blockIdx.y * GBM;
    const int colC = blockIdx.x * GBN;

    const int lrow  = (lane & 7) | (lane & 8);
    const int lcolA = (lane >> 4) << 2;

    const float* Aptr = A + (size_t)rowC * K;
    const float* Bptr = B + colC;

    const int a_r0 = tid >> 2,         a_c0 = (tid & 3) * 4;
    const int a_r1 = (tid + 256) >> 2, a_c1 = ((tid + 256) & 3) * 4;
    const int b_r0 = tid >> 5,         b_c0 = (tid & 31) * 4;
    const int b_r1 = (tid + 256) >> 5, b_c1 = ((tid + 256) & 31) * 4;

    const unsigned asBase = (unsigned)__cvta_generic_to_shared(AsF);
    const unsigned bsBase = (unsigned)__cvta_generic_to_shared(BsF);
    const unsigned aOff0 = (unsigned)(a_r0 * ASTR + a_c0) * 4;
    const unsigned aOff1 = (unsigned)(a_r1 * ASTR + a_c1) * 4;
    const unsigned bOff0 = (unsigned)(b_r0 * BSTR + b_c0) * 4;
    const unsigned bOff1 = (unsigned)(b_r1 * BSTR + b_c1) * 4;

    const unsigned aFragBase = (unsigned)__cvta_generic_to_shared(
        &AsF[(wm * 64 + lrow) * ASTR + lcolA]);

    float acc[4][4][4];
#pragma unroll
    for (int mt = 0; mt < 4; mt++)
#pragma unroll
        for (int nt = 0; nt < 4; nt++)
#pragma unroll
            for (int r = 0; r < 4; r++) acc[mt][nt][r] = 0.f;

    const int nk = K / GBK;   // 16

    // ---- prologue: stages 0..STAGES-2
#pragma unroll
    for (int s = 0; s < STAGES - 1; s++) {
        const int k0 = s * GBK;
        cp_async16(asBase + s * ABUF + aOff0, Aptr + (size_t)a_r0 * K + k0 + a_c0);
        cp_async16(asBase + s * ABUF + aOff1, Aptr + (size_t)a_r1 * K + k0 + a_c1);
        cp_async16(bsBase + s * BBUF + bOff0, Bptr + (size_t)(k0 + b_r0) * N + b_c0);
        cp_async16(bsBase + s * BBUF + bOff1, Bptr + (size_t)(k0 + b_r1) * N + b_c1);
        cp_commit();
    }
    asm volatile("cp.async.wait_group %0;" :: "n"(STAGES - 2));
    __syncthreads();

    int buf = 0;
    for (int kt = 0; kt < nk; kt++) {
        // issue stage kt+3 (overlaps this tile's MMA work)
        if (kt + STAGES - 1 < nk) {
            const int k0 = (kt + STAGES - 1) * GBK;
            const unsigned sb = (unsigned)((kt + STAGES - 1) & (STAGES - 1));
            cp_async16(asBase + sb * ABUF + aOff0, Aptr + (size_t)a_r0 * K + k0 + a_c0);
            cp_async16(asBase + sb * ABUF + aOff1, Aptr + (size_t)a_r1 * K + k0 + a_c1);
            cp_async16(bsBase + sb * BBUF + bOff0, Bptr + (size_t)(k0 + b_r0) * N + b_c0);
            cp_async16(bsBase + sb * BBUF + bOff1, Bptr + (size_t)(k0 + b_r1) * N + b_c1);
        }
        cp_commit();   // always commit (empty groups at tail keep accounting uniform)

        // ---- compute stage buf (no cvt: inputs pre-rounded)
        const unsigned aBuf = aFragBase + (unsigned)buf * ABUF;
        const float* Bstage = BsF + buf * BSTAGE_F;
#pragma unroll
        for (int s = 0; s < 2; s++) {
            const int k8 = s * 8;
            unsigned af[4][4];
#pragma unroll
            for (int mt = 0; mt < 4; mt++)
                ldsm4(af[mt], aBuf + mt * (16 * ASTR * 4) + k8 * 4);
#pragma unroll
            for (int nt = 0; nt < 4; nt++) {
                const int col = wn * 32 + nt * 8 + g;
                unsigned b0 = __float_as_uint(Bstage[(k8 + t) * BSTR + col]);
                unsigned b1 = __float_as_uint(Bstage[(k8 + t + 4) * BSTR + col]);
#pragma unroll
                for (int mt = 0; mt < 4; mt++)
                    mma_tf32(acc[mt][nt], af[mt], b0, b1);
            }
        }

        asm volatile("cp.async.wait_group %0;" :: "n"(STAGES - 2));
        __syncthreads();
        buf = (buf + 1) & (STAGES - 1);
    }

#pragma unroll
    for (int mt = 0; mt < 4; mt++) {
        const int r0 = rowC + wm * 64 + mt * 16 + g;
#pragma unroll
        for (int nt = 0; nt < 4; nt++) {
            const int cc = colC + wn * 32 + nt * 8 + 2 * t;
            const float bb0 = bias[cc], bb1 = bias[cc + 1];
            float2 o;
            o.x = acc[mt][nt][0] + bb0;
            o.y = acc[mt][nt][1] + bb1;
            *(float2*)&C[(size_t)r0 * N + cc] = o;
            o.x = acc[mt][nt][2] + bb0;
            o.y = acc[mt][nt][3] + bb1;
            *(float2*)&C[(size_t)(r0 + 8) * N + cc] = o;
        }
    }
}

// ---------------------------------------------------------------------------
// Tensor-core window attention: one CTA per (b, h), 4 warps.
// Warp-local softmax, ldmatrix fragments. Output stored tf32-rounded.
// ---------------------------------------------------------------------------
__global__ __launch_bounds__(128) void attn_mma_kernel(
    const float* __restrict__ qkv, const float* __restrict__ comb,
    float* __restrict__ out)
{
    const int h = blockIdx.x;
    const int b = blockIdx.y;

    __shared__ float qs[64][36];
    __shared__ float ks[56][36];
    __shared__ float vs[56][40];
    __shared__ float sc[64][68];

    const int tid   = threadIdx.x;
    const int lane  = tid & 31;
    const int wid   = tid >> 5;
    const int g     = lane >> 2;
    const int t     = lane & 3;
    const int lrow  = (lane & 7) | (lane & 8);
    const int lcolA = (lane >> 4) << 2;
    const float scale = 0.17677669529663687f;

    const float* base = qkv + (size_t)b * NSEQ * THREECD + h * DHEAD;
    for (int f = tid; f < NSEQ * 8; f += 128) {
        int n = f >> 3, c = (f & 7) << 2;
        const float* row = base + (size_t)n * THREECD;
        float4 q4 = *(const float4*)(row + c);
        float4 k4 = *(const float4*)(row + CDIM + c);
        float4 v4 = *(const float4*)(row + 2 * CDIM + c);
        float4 o;
        o.x = to_tf32(q4.x * scale); o.y = to_tf32(q4.y * scale);
        o.z = to_tf32(q4.z * scale); o.w = to_tf32(q4.w * scale);
        *(float4*)&qs[n][c] = o;
        o.x = to_tf32(k4.x); o.y = to_tf32(k4.y);
        o.z = to_tf32(k4.z); o.w = to_tf32(k4.w);
        *(float4*)&ks[n][c] = o;
        o.x = to_tf32(v4.x); o.y = to_tf32(v4.y);
        o.z = to_tf32(v4.z); o.w = to_tf32(v4.w);
        *(float4*)&vs[n][c] = o;
    }
    for (int z = tid; z < 7 * 40; z += 128) vs[NSEQ + z / 40][z % 40] = 0.f;
    __syncthreads();

    const int row = wid * 16;

    // ---- QK^T
    float c_sc[7][4];
#pragma unroll
    for (int nt = 0; nt < 7; nt++)
#pragma unroll
        for (int r = 0; r < 4; r++) c_sc[nt][r] = 0.f;

    const unsigned qAddr = (unsigned)__cvta_generic_to_shared(
        &qs[row + lrow][lcolA]);
#pragma unroll
    for (int kk = 0; kk < 4; kk++) {
        const int k8 = kk * 8;
        unsigned a[4];
        ldsm4(a, qAddr + kk * 32);
#pragma unroll
        for (int nt = 0; nt < 7; nt++) {
            unsigned b0 = __float_as_uint(ks[nt * 8 + g][k8 + t]);
            unsigned b1 = __float_as_uint(ks[nt * 8 + g][k8 + t + 4]);
            mma_tf32(c_sc[nt], a, b0, b1);
        }
    }

    // ---- epilogue + warp-local softmax
    const int r0 = row + g, r1 = r0 + 8;
    const float* cb = comb + ((size_t)(b & (NW - 1)) * NHEADS + h) * NSEQ * NSEQ;

    float mx0 = -CUDART_INF_F, mx1 = -CUDART_INF_F;
#pragma unroll
    for (int nt = 0; nt < 7; nt++) {
#pragma unroll
        for (int cx = 0; cx < 2; cx++) {
            const int cc = nt * 8 + 2 * t + cx;
            float v0 = (r0 < NSEQ && cc < NSEQ)
                     ? c_sc[nt][cx] + cb[r0 * NSEQ + cc] : -CUDART_INF_F;
            float v1 = (r1 < NSEQ && cc < NSEQ)
                     ? c_sc[nt][2 + cx] + cb[r1 * NSEQ + cc] : -CUDART_INF_F;
            c_sc[nt][cx] = v0;     mx0 = fmaxf(mx0, v0);
            c_sc[nt][2 + cx] = v1; mx1 = fmaxf(mx1, v1);
        }
    }
    mx0 = fmaxf(mx0, __shfl_xor_sync(0xffffffffu, mx0, 1));
    mx0 = fmaxf(mx0, __shfl_xor_sync(0xffffffffu, mx0, 2));
    mx1 = fmaxf(mx1, __shfl_xor_sync(0xffffffffu, mx1, 1));
    mx1 = fmaxf(mx1, __shfl_xor_sync(0xffffffffu, mx1, 2));

    float s0 = 0.f, s1 = 0.f;
#pragma unroll
    for (int nt = 0; nt < 7; nt++) {
#pragma unroll
        for (int cx = 0; cx < 2; cx++) {
            float e0 = __expf(c_sc[nt][cx] - mx0);
            float e1 = __expf(c_sc[nt][2 + cx] - mx1);
            c_sc[nt][cx] = e0;     s0 += e0;
            c_sc[nt][2 + cx] = e1; s1 += e1;
        }
    }
    s0 += __shfl_xor_sync(0xffffffffu, s0, 1);
    s0 += __shfl_xor_sync(0xffffffffu, s0, 2);
    s1 += __shfl_xor_sync(0xffffffffu, s1, 1);
    s1 += __shfl_xor_sync(0xffffffffu, s1, 2);
    const float inv0 = 1.f / s0, inv1 = 1.f / s1;

#pragma unroll
    for (int nt = 0; nt < 7; nt++) {
        float2 p;
        p.x = c_sc[nt][0] * inv0; p.y = c_sc[nt][1] * inv0;
        *(float2*)&sc[r0][nt * 8 + 2 * t] = p;
        p.x = c_sc[nt][2] * inv1; p.y = c_sc[nt][3] * inv1;
        *(float2*)&sc[r1][nt * 8 + 2 * t] = p;
    }
    __syncwarp();

    // ---- AV (split-tf32 on P)
    float c_o[4][4];
#pragma unroll
    for (int nt = 0; nt < 4; nt++)
#pragma unroll
        for (int r = 0; r < 4; r++) c_o[nt][r] = 0.f;

    const unsigned pAddr = (unsigned)__cvta_generic_to_shared(
        &sc[row + lrow][lcolA]);
#pragma unroll
    for (int kk = 0; kk < 7; kk++) {
        const int k8 = kk * 8;
        unsigned praw[4];
        ldsm4(praw, pAddr + kk * 32);
        unsigned ah[4], al[4];
#pragma unroll
        for (int r = 0; r < 4; r++) {
            float f = __uint_as_float(praw[r]);
            float hi = to_tf32(f);
            ah[r] = __float_as_uint(hi);
            al[r] = __float_as_uint(to_tf32(f - hi));
        }
#pragma unroll
        for (int nt = 0; nt < 4; nt++) {
            unsigned b0 = __float_as_uint(vs[k8 + t][nt * 8 + g]);
            unsigned b1 = __float_as_uint(vs[k8 + t + 4][nt * 8 + g]);
            mma_tf32(c_o[nt], ah, b0, b1);
            mma_tf32(c_o[nt], al, b0, b1);
        }
    }

    // store tf32-rounded so GEMM2 needs no in-loop cvt
    float* obase = out + (size_t)b * NSEQ * CDIM + h * DHEAD;
#pragma unroll
    for (int nt = 0; nt < 4; nt++) {
        const int dd = nt * 8 + 2 * t;
        if (r0 < NSEQ) {
            float2 o; o.x = to_tf32(c_o[nt][0]); o.y = to_tf32(c_o[nt][1]);
            *(float2*)&obase[(size_t)r0 * CDIM + dd] = o;
        }
        if (r1 < NSEQ) {
            float2 o; o.x = to_tf32(c_o[nt][2]); o.y = to_tf32(c_o[nt][3]);
            *(float2*)&obase[(size_t)r1 * CDIM + dd] = o;
        }
    }
}

// ---------------------------------------------------------------------------
extern "C" void kernel_launch(void* const* d_in, const int* in_sizes, int n_in,
                              void* d_out, int out_size)
{
    const float* x          = (const float*)d_in[0];
    const float* mask       = (const float*)d_in[1];
    const float* qkv_w      = (const float*)d_in[2];
    const float* qkv_b      = (const float*)d_in[3];
    const float* proj_w     = (const float*)d_in[4];
    const float* proj_b     = (const float*)d_in[5];
    const float* bias_table = (const float*)d_in[6];
    float* out = (float*)d_out;

    float *qkv_ptr, *ao_ptr, *comb_ptr, *xr_ptr, *wqkv_ptr, *wproj_ptr;
    cudaGetSymbolAddress((void**)&qkv_ptr, g_qkv);
    cudaGetSymbolAddress((void**)&ao_ptr, g_attnout);
    cudaGetSymbolAddress((void**)&comb_ptr, g_comb);
    cudaGetSymbolAddress((void**)&xr_ptr, g_xr);
    cudaGetSymbolAddress((void**)&wqkv_ptr, g_wqkv);
    cudaGetSymbolAddress((void**)&wproj_ptr, g_wproj);

    static bool smem_set = false;
    if (!smem_set) {
        cudaFuncSetAttribute(gemm_tf32_kernel,
                             cudaFuncAttributeMaxDynamicSharedMemorySize, GEMM_SMEM);
        smem_set = true;
    }

    const int M = B_TOT * NSEQ;  // 100352

    // 0) pre-round inputs to tf32
    {
        int n4 = M * CDIM / 4;
        round_tf32_kernel<<<(n4 + 255) / 256, 256>>>((const float4*)x, (float4*)xr_ptr, n4);
        n4 = CDIM * THREECD / 4;
        round_tf32_kernel<<<(n4 + 255) / 256, 256>>>((const float4*)qkv_w, (float4*)wqkv_ptr, n4);
        n4 = CDIM * CDIM / 4;
        round_tf32_kernel<<<(n4 + 255) / 256, 256>>>((const float4*)proj_w, (float4*)wproj_ptr, n4);
    }
    {
        dim3 grid(NW, NHEADS);
        combine_kernel<<<grid, 128>>>(mask, bias_table, comb_ptr);
    }
    // 1) qkv = xr @ wqkv + qkv_b
    {
        dim3 grid(THREECD / GBN, M / GBM);
        gemm_tf32_kernel<<<grid, 256, GEMM_SMEM>>>(xr_ptr, wqkv_ptr, qkv_b, qkv_ptr,
                                                   M, CDIM, THREECD);
    }
    // 2) window attention
    {
        dim3 grid(NHEADS, B_TOT);
        attn_mma_kernel<<<grid, 128>>>(qkv_ptr, comb_ptr, ao_ptr);
    }
    // 3) out = attnout @ wproj + proj_b
    {
        dim3 grid(CDIM / GBN, M / GBM);
        gemm_tf32_kernel<<<grid, 256, GEMM_SMEM>>>(ao_ptr, wproj_ptr, proj_b, out,
                                                   M, CDIM, CDIM);
    }
}

// round 7
// speedup vs baseline: 5.5790x; 1.4687x over previous
#include <cuda_runtime.h>
#include <cuda_fp16.h>
#include <math_constants.h>

// Problem constants
#define B_TOT   2048
#define NSEQ    49
#define CDIM    256
#define NHEADS  8
#define DHEAD   32
#define NW      64
#define THREECD 768

// Scratch (allocation-free rule: __device__ globals)
__device__ __align__(16) __half g_xh[(size_t)B_TOT * NSEQ * CDIM];      // x fp16
__device__ __align__(16) __half g_wqkvh[(size_t)CDIM * THREECD];        // qkv_w fp16
__device__ __align__(16) __half g_wprojh[(size_t)CDIM * CDIM];          // proj_w fp16
__device__ __align__(16) __half g_qkvh[(size_t)B_TOT * NSEQ * THREECD]; // qkv fp16
__device__ __align__(16) __half g_aoh[(size_t)B_TOT * NSEQ * CDIM];     // attn out fp16
__device__ float g_comb[(size_t)NW * NHEADS * NSEQ * NSEQ];             // bias+mask

__device__ __forceinline__ void mma_f16(float (&c)[4], const unsigned (&a)[4],
                                        unsigned b0, unsigned b1) {
    asm volatile(
        "mma.sync.aligned.m16n8k16.row.col.f32.f16.f16.f32 "
        "{%0,%1,%2,%3}, {%4,%5,%6,%7}, {%8,%9}, {%0,%1,%2,%3};\n"
        : "+f"(c[0]), "+f"(c[1]), "+f"(c[2]), "+f"(c[3])
        : "r"(a[0]), "r"(a[1]), "r"(a[2]), "r"(a[3]), "r"(b0), "r"(b1));
}

__device__ __forceinline__ void ldsm4(unsigned (&r)[4], unsigned addr) {
    asm volatile("ldmatrix.sync.aligned.m8n8.x4.shared.b16 {%0,%1,%2,%3}, [%4];"
        : "=r"(r[0]), "=r"(r[1]), "=r"(r[2]), "=r"(r[3]) : "r"(addr));
}
__device__ __forceinline__ void ldsm4t(unsigned (&r)[4], unsigned addr) {
    asm volatile("ldmatrix.sync.aligned.m8n8.x4.trans.shared.b16 {%0,%1,%2,%3}, [%4];"
        : "=r"(r[0]), "=r"(r[1]), "=r"(r[2]), "=r"(r[3]) : "r"(addr));
}

__device__ __forceinline__ void cp_async16(unsigned smem_addr, const void* gptr) {
    asm volatile("cp.async.cg.shared.global [%0], [%1], 16;"
                 :: "r"(smem_addr), "l"(gptr));
}
__device__ __forceinline__ void cp_commit() {
    asm volatile("cp.async.commit_group;");
}

// ---------------------------------------------------------------------------
// f32 -> f16 conversion pass (float4 -> 4 halves)
// ---------------------------------------------------------------------------
__global__ void f32_to_f16_kernel(const float4* __restrict__ src,
                                  uint2* __restrict__ dst, int n4)
{
    int i = blockIdx.x * blockDim.x + threadIdx.x;
    if (i < n4) {
        float4 v = src[i];
        __half2 h0 = __floats2half2_rn(v.x, v.y);
        __half2 h1 = __floats2half2_rn(v.z, v.w);
        uint2 o;
        o.x = *(unsigned*)&h0;
        o.y = *(unsigned*)&h1;
        dst[i] = o;
    }
}

// ---------------------------------------------------------------------------
// comb[w][h][i][j] = mask[w][i][j] + bias_table[rpi(i,j)][h]
// ---------------------------------------------------------------------------
__global__ void combine_kernel(const float* __restrict__ mask,
                               const float* __restrict__ bias_table,
                               float* __restrict__ comb)
{
    const int w = blockIdx.x, h = blockIdx.y;
    const float* mrow = mask + (size_t)w * NSEQ * NSEQ;
    float* crow = comb + ((size_t)w * NHEADS + h) * NSEQ * NSEQ;
    for (int p = threadIdx.x; p < NSEQ * NSEQ; p += blockDim.x) {
        int i = p / NSEQ, j = p - (p / NSEQ) * NSEQ;
        int i0 = i / 7, i1 = i - i0 * 7;
        int j0 = j / 7, j1 = j - j0 * 7;
        int ridx = (i0 - j0 + 6) * 13 + (i1 - j1 + 6);
        crow[p] = mrow[p] + bias_table[ridx * NHEADS + h];
    }
}

// ---------------------------------------------------------------------------
// FP16 tensor-core GEMM: C[M,N] = A[M,K] @ B[K,N] + bias[N]
// CTA 128x128, BK=16, 8 warps (2m x 4n), warp tile 64x32.
// 4-stage cp.async; A frags ldsm.x4, B frags ldsm.x4.trans; f32 accumulate.
// ---------------------------------------------------------------------------
#define GBM 128
#define GBN 128
#define GBK 16
#define ASTR 24      // halves per A row (48B, 16B-aligned, ldsm conflict-free)
#define BSTR 136     // halves per B row (272B)
#define STAGES 4
#define ABUF (GBM * ASTR * 2)                 // 6144 B per A stage
#define BBUF (GBK * BSTR * 2)                 // 4352 B per B stage
#define GEMM_SMEM (STAGES * (ABUF + BBUF))    // 41984 B

template <bool OUT_HALF>
__global__ __launch_bounds__(256, 2) void gemm_f16_kernel(
    const __half* __restrict__ A, const __half* __restrict__ B,
    const float* __restrict__ bias, void* __restrict__ Cv,
    int M, int K, int N)
{
    extern __shared__ __half sm[];
    __half* AsH = sm;                              // STAGES*128*ASTR
    __half* BsH = sm + STAGES * GBM * ASTR;        // STAGES*16*BSTR

    const int tid  = threadIdx.x;
    const int wid  = tid >> 5;
    const int lane = tid & 31;
    const int wm   = wid & 1;
    const int wn   = wid >> 1;
    const int g    = lane >> 2;
    const int t    = lane & 3;
    const int rowC = blockIdx.y * GBM;
    const int colC = blockIdx.x * GBN;

    const __half* Aptr = A + (size_t)rowC * K;
    const __half* Bptr = B + colC;

    const int a_r = tid >> 1, a_c = (tid & 1) * 8;
    const int b_r = tid >> 4, b_c = (tid & 15) * 8;

    const unsigned asBase = (unsigned)__cvta_generic_to_shared(AsH);
    const unsigned bsBase = (unsigned)__cvta_generic_to_shared(BsH);
    const unsigned aOff = (unsigned)(a_r * ASTR + a_c) * 2;
    const unsigned bOff = (unsigned)(b_r * BSTR + b_c) * 2;

    const unsigned aFragBase = (unsigned)__cvta_generic_to_shared(
        &AsH[(wm * 64 + (lane & 15)) * ASTR + ((lane >> 4) << 3)]);
    const unsigned bFragBase = (unsigned)__cvta_generic_to_shared(
        &BsH[(lane & 15) * BSTR + wn * 32 + ((lane >> 4) << 3)]);

    float acc[4][4][4];
#pragma unroll
    for (int mt = 0; mt < 4; mt++)
#pragma unroll
        for (int nt = 0; nt < 4; nt++)
#pragma unroll
            for (int r = 0; r < 4; r++) acc[mt][nt][r] = 0.f;

    const int nk = K / GBK;   // 16

#pragma unroll
    for (int s = 0; s < STAGES - 1; s++) {
        const int k0 = s * GBK;
        cp_async16(asBase + s * ABUF + aOff, Aptr + (size_t)a_r * K + k0 + a_c);
        cp_async16(bsBase + s * BBUF + bOff, Bptr + (size_t)(k0 + b_r) * N + b_c);
        cp_commit();
    }
    asm volatile("cp.async.wait_group %0;" :: "n"(STAGES - 2));
    __syncthreads();

    int buf = 0;
    for (int kt = 0; kt < nk; kt++) {
        if (kt + STAGES - 1 < nk) {
            const int k0 = (kt + STAGES - 1) * GBK;
            const unsigned sb = (unsigned)((kt + STAGES - 1) & (STAGES - 1));
            cp_async16(asBase + sb * ABUF + aOff, Aptr + (size_t)a_r * K + k0 + a_c);
            cp_async16(bsBase + sb * BBUF + bOff, Bptr + (size_t)(k0 + b_r) * N + b_c);
        }
        cp_commit();

        unsigned af[4][4], bf[2][4];
#pragma unroll
        for (int mt = 0; mt < 4; mt++)
            ldsm4(af[mt], aFragBase + buf * ABUF + mt * (16 * ASTR * 2));
#pragma unroll
        for (int blk = 0; blk < 2; blk++)
            ldsm4t(bf[blk], bFragBase + buf * BBUF + blk * 16 * 2);
#pragma unroll
        for (int nt = 0; nt < 4; nt++) {
            const unsigned b0 = bf[nt >> 1][(nt & 1) * 2];
            const unsigned b1 = bf[nt >> 1][(nt & 1) * 2 + 1];
#pragma unroll
            for (int mt = 0; mt < 4; mt++)
                mma_f16(acc[mt][nt], af[mt], b0, b1);
        }

        asm volatile("cp.async.wait_group %0;" :: "n"(STAGES - 2));
        __syncthreads();
        buf = (buf + 1) & (STAGES - 1);
    }

#pragma unroll
    for (int mt = 0; mt < 4; mt++) {
        const int r0 = rowC + wm * 64 + mt * 16 + g;
#pragma unroll
        for (int nt = 0; nt < 4; nt++) {
            const int cc = colC + wn * 32 + nt * 8 + 2 * t;
            const float bb0 = bias[cc], bb1 = bias[cc + 1];
            if (OUT_HALF) {
                __half* C = (__half*)Cv;
                *(__half2*)&C[(size_t)r0 * N + cc] =
                    __floats2half2_rn(acc[mt][nt][0] + bb0, acc[mt][nt][1] + bb1);
                *(__half2*)&C[(size_t)(r0 + 8) * N + cc] =
                    __floats2half2_rn(acc[mt][nt][2] + bb0, acc[mt][nt][3] + bb1);
            } else {
                float* C = (float*)Cv;
                float2 o;
                o.x = acc[mt][nt][0] + bb0; o.y = acc[mt][nt][1] + bb1;
                *(float2*)&C[(size_t)r0 * N + cc] = o;
                o.x = acc[mt][nt][2] + bb0; o.y = acc[mt][nt][3] + bb1;
                *(float2*)&C[(size_t)(r0 + 8) * N + cc] = o;
            }
        }
    }
}

// ---------------------------------------------------------------------------
// FP16 tensor-core window attention: one CTA per (b, h), 4 warps.
// ---------------------------------------------------------------------------
#define QSTR 40      // halves per q/k/v row (80B)
#define SCSTR 72     // halves per P row (144B)

__global__ __launch_bounds__(128) void attn_mma_kernel(
    const __half* __restrict__ qkv, const float* __restrict__ comb,
    __half* __restrict__ out)
{
    const int h = blockIdx.x;
    const int b = blockIdx.y;

    __shared__ __half qs[64][QSTR];
    __shared__ __half ks[64][QSTR];
    __shared__ __half vs[64][QSTR];
    __shared__ __half sch[64][SCSTR];
    __shared__ __half scl[64][SCSTR];

    const int tid  = threadIdx.x;
    const int lane = tid & 31;
    const int wid  = tid >> 5;
    const int g    = lane >> 2;
    const int t    = lane & 3;
    const float scale = 0.17677669529663687f;  // 32^-0.5

    const __half* base = qkv + (size_t)b * NSEQ * THREECD + h * DHEAD;
    for (int f = tid; f < NSEQ * 8; f += 128) {
        int n = f >> 3, c = (f & 7) << 2;
        const __half* row = base + (size_t)n * THREECD;
        *(uint2*)&qs[n][c] = *(const uint2*)(row + c);
        *(uint2*)&ks[n][c] = *(const uint2*)(row + CDIM + c);
        *(uint2*)&vs[n][c] = *(const uint2*)(row + 2 * CDIM + c);
    }
    for (int z = tid; z < 15 * QSTR; z += 128)
        vs[NSEQ + z / QSTR][z % QSTR] = __ushort_as_half(0);
    __syncthreads();

    const int row = wid * 16;

    float c_sc[7][4];
#pragma unroll
    for (int nt = 0; nt < 7; nt++)
#pragma unroll
        for (int r = 0; r < 4; r++) c_sc[nt][r] = 0.f;

    const unsigned qAddr = (unsigned)__cvta_generic_to_shared(
        &qs[row + (lane & 15)][(lane >> 4) << 3]);
    const unsigned kAddr = (unsigned)__cvta_generic_to_shared(
        &ks[(lane & 7) + ((lane >> 4) << 3)][((lane >> 3) & 1) << 3]);

#pragma unroll
    for (int kc = 0; kc < 2; kc++) {
        const int k0 = kc * 16;
        unsigned a[4];
        ldsm4(a, qAddr + k0 * 2);
        unsigned bf[4][4];
#pragma unroll
        for (int jb = 0; jb < 4; jb++)
            ldsm4(bf[jb], kAddr + (jb * 16 * QSTR + k0) * 2);
#pragma unroll
        for (int nt = 0; nt < 7; nt++) {
            const unsigned b0 = bf[nt >> 1][(nt & 1) * 2];
            const unsigned b1 = bf[nt >> 1][(nt & 1) * 2 + 1];
            mma_f16(c_sc[nt], a, b0, b1);
        }
    }

    const int r0 = row + g, r1 = r0 + 8;
    const float* cb = comb + ((size_t)(b & (NW - 1)) * NHEADS + h) * NSEQ * NSEQ;

    float mx0 = -1e30f, mx1 = -1e30f;
#pragma unroll
    for (int nt = 0; nt < 7; nt++) {
#pragma unroll
        for (int cx = 0; cx < 2; cx++) {
            const int cc = nt * 8 + 2 * t + cx;
            float v0 = (r0 < NSEQ && cc < NSEQ)
                     ? fmaf(c_sc[nt][cx], scale, cb[r0 * NSEQ + cc]) : -1e30f;
            float v1 = (r1 < NSEQ && cc < NSEQ)
                     ? fmaf(c_sc[nt][2 + cx], scale, cb[r1 * NSEQ + cc]) : -1e30f;
            c_sc[nt][cx] = v0;     mx0 = fmaxf(mx0, v0);
            c_sc[nt][2 + cx] = v1; mx1 = fmaxf(mx1, v1);
        }
    }
    mx0 = fmaxf(mx0, __shfl_xor_sync(0xffffffffu, mx0, 1));
    mx0 = fmaxf(mx0, __shfl_xor_sync(0xffffffffu, mx0, 2));
    mx1 = fmaxf(mx1, __shfl_xor_sync(0xffffffffu, mx1, 1));
    mx1 = fmaxf(mx1, __shfl_xor_sync(0xffffffffu, mx1, 2));

    float s0 = 0.f, s1 = 0.f;
#pragma unroll
    for (int nt = 0; nt < 7; nt++) {
#pragma unroll
        for (int cx = 0; cx < 2; cx++) {
            float e0 = __expf(c_sc[nt][cx] - mx0);
            float e1 = __expf(c_sc[nt][2 + cx] - mx1);
            c_sc[nt][cx] = e0;     s0 += e0;
            c_sc[nt][2 + cx] = e1; s1 += e1;
        }
    }
    s0 += __shfl_xor_sync(0xffffffffu, s0, 1);
    s0 += __shfl_xor_sync(0xffffffffu, s0, 2);
    s1 += __shfl_xor_sync(0xffffffffu, s1, 1);
    s1 += __shfl_xor_sync(0xffffffffu, s1, 2);
    const float inv0 = 1.f / s0, inv1 = 1.f / s1;

#pragma unroll
    for (int nt = 0; nt < 7; nt++) {
        const int cc = nt * 8 + 2 * t;
        float p00 = (cc     < NSEQ) ? c_sc[nt][0] * inv0 : 0.f;
        float p01 = (cc + 1 < NSEQ) ? c_sc[nt][1] * inv0 : 0.f;
        float p10 = (cc     < NSEQ) ? c_sc[nt][2] * inv1 : 0.f;
        float p11 = (cc + 1 < NSEQ) ? c_sc[nt][3] * inv1 : 0.f;
        __half2 h0 = __floats2half2_rn(p00, p01);
        __half2 h1 = __floats2half2_rn(p10, p11);
        *(__half2*)&sch[r0][cc] = h0;
        *(__half2*)&sch[r1][cc] = h1;
        *(__half2*)&scl[r0][cc] = __floats2half2_rn(
            p00 - __half2float(__low2half(h0)), p01 - __half2float(__high2half(h0)));
        *(__half2*)&scl[r1][cc] = __floats2half2_rn(
            p10 - __half2float(__low2half(h1)), p11 - __half2float(__high2half(h1)));
    }
    {
        const int cc = 56 + 2 * t;
        *(unsigned*)&sch[r0][cc] = 0u;
        *(unsigned*)&sch[r1][cc] = 0u;
        *(unsigned*)&scl[r0][cc] = 0u;
        *(unsigned*)&scl[r1][cc] = 0u;
    }
    __syncwarp();

    float c_o[4][4];
#pragma unroll
    for (int nt = 0; nt < 4; nt++)
#pragma unroll
        for (int r = 0; r < 4; r++) c_o[nt][r] = 0.f;

    const unsigned phAddr = (unsigned)__cvta_generic_to_shared(
        &sch[row + (lane & 15)][(lane >> 4) << 3]);
    const unsigned plAddr = (unsigned)__cvta_generic_to_shared(
        &scl[row + (lane & 15)][(lane >> 4) << 3]);
    const unsigned vAddr = (unsigned)__cvta_generic_to_shared(
        &vs[lane & 15][(lane >> 4) << 3]);

#pragma unroll
    for (int kc = 0; kc < 4; kc++) {
        const int k0 = kc * 16;
        unsigned ah[4], al[4];
        ldsm4(ah, phAddr + k0 * 2);
        ldsm4(al, plAddr + k0 * 2);
        unsigned bf[2][4];
#pragma unroll
        for (int db = 0; db < 2; db++)
            ldsm4t(bf[db], vAddr + (k0 * QSTR + db * 16) * 2);
#pragma unroll
        for (int nt = 0; nt < 4; nt++) {
            const unsigned b0 = bf[nt >> 1][(nt & 1) * 2];
            const unsigned b1 = bf[nt >> 1][(nt & 1) * 2 + 1];
            mma_f16(c_o[nt], ah, b0, b1);
            mma_f16(c_o[nt], al, b0, b1);
        }
    }

    __half* obase = out + (size_t)b * NSEQ * CDIM + h * DHEAD;
#pragma unroll
    for (int nt = 0; nt < 4; nt++) {
        const int dd = nt * 8 + 2 * t;
        if (r0 < NSEQ)
            *(__half2*)&obase[(size_t)r0 * CDIM + dd] =
                __floats2half2_rn(c_o[nt][0], c_o[nt][1]);
        if (r1 < NSEQ)
            *(__half2*)&obase[(size_t)r1 * CDIM + dd] =
                __floats2half2_rn(c_o[nt][2], c_o[nt][3]);
    }
}

// ---------------------------------------------------------------------------
extern "C" void kernel_launch(void* const* d_in, const int* in_sizes, int n_in,
                              void* d_out, int out_size)
{
    const float* x          = (const float*)d_in[0];
    const float* mask       = (const float*)d_in[1];
    const float* qkv_w      = (const float*)d_in[2];
    const float* qkv_b      = (const float*)d_in[3];
    const float* proj_w     = (const float*)d_in[4];
    const float* proj_b     = (const float*)d_in[5];
    const float* bias_table = (const float*)d_in[6];
    float* out = (float*)d_out;

    __half *xh, *wqkvh, *wprojh, *qkvh, *aoh;
    float *comb_ptr;
    cudaGetSymbolAddress((void**)&xh, g_xh);
    cudaGetSymbolAddress((void**)&wqkvh, g_wqkvh);
    cudaGetSymbolAddress((void**)&wprojh, g_wprojh);
    cudaGetSymbolAddress((void**)&qkvh, g_qkvh);
    cudaGetSymbolAddress((void**)&aoh, g_aoh);
    cudaGetSymbolAddress((void**)&comb_ptr, g_comb);

    static bool smem_set = false;
    if (!smem_set) {
        cudaFuncSetAttribute(gemm_f16_kernel<true>,
                             cudaFuncAttributeMaxDynamicSharedMemorySize, GEMM_SMEM);
        cudaFuncSetAttribute(gemm_f16_kernel<false>,
                             cudaFuncAttributeMaxDynamicSharedMemorySize, GEMM_SMEM);
        smem_set = true;
    }

    const int M = B_TOT * NSEQ;  // 100352

    {
        int n4 = M * CDIM / 4;
        f32_to_f16_kernel<<<(n4 + 255) / 256, 256>>>((const float4*)x, (uint2*)xh, n4);
        n4 = CDIM * THREECD / 4;
        f32_to_f16_kernel<<<(n4 + 255) / 256, 256>>>((const float4*)qkv_w, (uint2*)wqkvh, n4);
        n4 = CDIM * CDIM / 4;
        f32_to_f16_kernel<<<(n4 + 255) / 256, 256>>>((const float4*)proj_w, (uint2*)wprojh, n4);
    }
    {
        dim3 grid(NW, NHEADS);
        combine_kernel<<<grid, 128>>>(mask, bias_table, comb_ptr);
    }
    {
        dim3 grid(THREECD / GBN, M / GBM);
        gemm_f16_kernel<true><<<grid, 256, GEMM_SMEM>>>(xh, wqkvh, qkv_b, qkvh,
                                                        M, CDIM, THREECD);
    }
    {
        dim3 grid(NHEADS, B_TOT);
        attn_mma_kernel<<<grid, 128>>>(qkvh, comb_ptr, aoh);
    }
    {
        dim3 grid(CDIM / GBN, M / GBM);
        gemm_f16_kernel<false><<<grid, 256, GEMM_SMEM>>>(aoh, wprojh, proj_b, out,
                                                         M, CDIM, CDIM);
    }
}

// round 10
// speedup vs baseline: 5.8597x; 1.0503x over previous
#include <cuda_runtime.h>
#include <cuda_fp16.h>
#include <cstdint>

// Problem constants
#define B_TOT   2048
#define NSEQ    49
#define CDIM    256
#define NHEADS  8
#define DHEAD   32
#define NW      64
#define THREECD 768

// Scratch (allocation-free rule: __device__ globals)
__device__ __align__(16) __half g_xh[(size_t)B_TOT * NSEQ * CDIM];       // x fp16
__device__ __align__(16) __half g_wqkvh[(size_t)CDIM * THREECD];         // qkv_w fp16
__device__ __align__(16) __half g_wprojh[(size_t)CDIM * CDIM];           // proj_w fp16
__device__ __align__(16) __half g_qkvh[(size_t)B_TOT * NSEQ * THREECD];  // qkv fp16
__device__ __align__(16) __half g_aoh[(size_t)B_TOT * NSEQ * CDIM];      // attn out fp16
__device__ float g_comb[(size_t)NW * NHEADS * NSEQ * NSEQ];              // bias+mask

// ---------------------------------------------------------------------------
// PTX helpers (legacy mma path — tcgen05 unavailable: harness PTX target is
// sm_103 without the 'a' feature set)
// ---------------------------------------------------------------------------
__device__ __forceinline__ void mma_f16(float (&c)[4], const unsigned (&a)[4],
                                        unsigned b0, unsigned b1) {
    asm volatile(
        "mma.sync.aligned.m16n8k16.row.col.f32.f16.f16.f32 "
        "{%0,%1,%2,%3}, {%4,%5,%6,%7}, {%8,%9}, {%0,%1,%2,%3};\n"
        : "+f"(c[0]), "+f"(c[1]), "+f"(c[2]), "+f"(c[3])
        : "r"(a[0]), "r"(a[1]), "r"(a[2]), "r"(a[3]), "r"(b0), "r"(b1));
}
__device__ __forceinline__ void ldsm4(unsigned (&r)[4], unsigned addr) {
    asm volatile("ldmatrix.sync.aligned.m8n8.x4.shared.b16 {%0,%1,%2,%3}, [%4];"
        : "=r"(r[0]), "=r"(r[1]), "=r"(r[2]), "=r"(r[3]) : "r"(addr));
}
__device__ __forceinline__ void ldsm4t(unsigned (&r)[4], unsigned addr) {
    asm volatile("ldmatrix.sync.aligned.m8n8.x4.trans.shared.b16 {%0,%1,%2,%3}, [%4];"
        : "=r"(r[0]), "=r"(r[1]), "=r"(r[2]), "=r"(r[3]) : "r"(addr));
}
__device__ __forceinline__ void cp_async16(unsigned smem_addr, const void* gptr) {
    asm volatile("cp.async.cg.shared.global [%0], [%1], 16;"
                 :: "r"(smem_addr), "l"(gptr));
}
__device__ __forceinline__ void cp_commit() {
    asm volatile("cp.async.commit_group;");
}

// ---------------------------------------------------------------------------
// Fused prepass: x->fp16 | qkv_w->fp16 transpose-less copy? No: plain convert |
// proj_w convert | comb table. (weights stay [K,N] row-major for ldsm.trans B)
// Grid sections, 256 threads per block.
// ---------------------------------------------------------------------------
#define NB_X   25088   // M*CDIM/4 / 256 = 6422528/256
#define NB_WQ  (CDIM * THREECD / 4 / 256)   // 192
#define NB_WP  (CDIM * CDIM / 4 / 256)      // 64
#define NB_CB  (NW * NHEADS)                // 512
#define NB_TOTAL (NB_X + NB_WQ + NB_WP + NB_CB)

__global__ __launch_bounds__(256) void prepass_kernel(
    const float4* __restrict__ x4, uint2* __restrict__ xh4,
    const float4* __restrict__ wq4, uint2* __restrict__ wqh4,
    const float4* __restrict__ wp4, uint2* __restrict__ wph4,
    const float* __restrict__ mask, const float* __restrict__ bias_table,
    float* __restrict__ comb)
{
    const int bid = blockIdx.x;
    const int tid = threadIdx.x;

    if (bid < NB_X + NB_WQ + NB_WP) {
        const float4* src;
        uint2* dst;
        int idx;
        if (bid < NB_X) {
            src = x4; dst = xh4; idx = bid * 256 + tid;
        } else if (bid < NB_X + NB_WQ) {
            src = wq4; dst = wqh4; idx = (bid - NB_X) * 256 + tid;
        } else {
            src = wp4; dst = wph4; idx = (bid - NB_X - NB_WQ) * 256 + tid;
        }
        float4 v = src[idx];
        __half2 h0 = __floats2half2_rn(v.x, v.y);
        __half2 h1 = __floats2half2_rn(v.z, v.w);
        uint2 o;
        o.x = *(unsigned*)&h0;
        o.y = *(unsigned*)&h1;
        dst[idx] = o;
    } else {
        const int b2 = bid - NB_X - NB_WQ - NB_WP;
        const int w = b2 & (NW - 1), h = b2 >> 6;
        const float* mrow = mask + (size_t)w * NSEQ * NSEQ;
        float* crow = comb + ((size_t)w * NHEADS + h) * NSEQ * NSEQ;
        for (int p = tid; p < NSEQ * NSEQ; p += 256) {
            int i = p / NSEQ, j = p - (p / NSEQ) * NSEQ;
            int i0 = i / 7, i1 = i - i0 * 7;
            int j0 = j / 7, j1 = j - j0 * 7;
            int ridx = (i0 - j0 + 6) * 13 + (i1 - j1 + 6);
            crow[p] = mrow[p] + bias_table[ridx * NHEADS + h];
        }
    }
}

// ---------------------------------------------------------------------------
// FP16 tensor-core GEMM: C[M,N] = A[M,K] @ B[K,N] + bias[N]
// CTA 128x128, BK=32 (8 k-iters), 8 warps (2m x 4n), warp tile 64x32.
// 4-stage cp.async; A frags ldsm.x4, B frags ldsm.x4.trans; f32 accumulate.
// ---------------------------------------------------------------------------
#define GBM 128
#define GBN 128
#define GBK 32
#define ASTR 40      // halves per A row (80B; ldsm conflict-free)
#define BSTR 136     // halves per B row (272B; trans-ldsm conflict-free)
#define STAGES 4
#define ABUF (GBM * ASTR * 2)                 // 10240 B per A stage
#define BBUF (GBK * BSTR * 2)                 // 8704 B per B stage
#define GEMM_SMEM (STAGES * (ABUF + BBUF))    // 75776 B

template <bool OUT_HALF>
__global__ __launch_bounds__(256, 2) void gemm_f16_kernel(
    const __half* __restrict__ A, const __half* __restrict__ B,
    const float* __restrict__ bias, void* __restrict__ Cv,
    int M, int K, int N)
{
    extern __shared__ __half sm[];
    __half* AsH = sm;                              // STAGES*128*ASTR
    __half* BsH = sm + STAGES * GBM * ASTR;        // STAGES*32*BSTR

    const int tid  = threadIdx.x;
    const int wid  = tid >> 5;
    const int lane = tid & 31;
    const int wm   = wid & 1;
    const int wn   = wid >> 1;
    const int g    = lane >> 2;
    const int t    = lane & 3;
    const int rowC = blockIdx.y * GBM;
    const int colC = blockIdx.x * GBN;

    const __half* Aptr = A + (size_t)rowC * K;
    const __half* Bptr = B + colC;

    // cp.async loader mapping: 2 chunks of 16B per thread for A, 2 for B
    // A stage: 128 rows x 32 halves (64B/row -> 4 chunks/row)
    const int a_q0 = tid,        a_q1 = tid + 256;
    const int a_r0 = a_q0 >> 2,  a_c0 = (a_q0 & 3) * 8;
    const int a_r1 = a_q1 >> 2,  a_c1 = (a_q1 & 3) * 8;
    // B stage: 32 rows x 128 halves (256B/row -> 16 chunks/row)
    const int b_q0 = tid,        b_q1 = tid + 256;
    const int b_r0 = b_q0 >> 4,  b_c0 = (b_q0 & 15) * 8;
    const int b_r1 = b_q1 >> 4,  b_c1 = (b_q1 & 15) * 8;

    const unsigned asBase = (unsigned)__cvta_generic_to_shared(AsH);
    const unsigned bsBase = (unsigned)__cvta_generic_to_shared(BsH);
    const unsigned aOff0 = (unsigned)(a_r0 * ASTR + a_c0) * 2;
    const unsigned aOff1 = (unsigned)(a_r1 * ASTR + a_c1) * 2;
    const unsigned bOff0 = (unsigned)(b_r0 * BSTR + b_c0) * 2;
    const unsigned bOff1 = (unsigned)(b_r1 * BSTR + b_c1) * 2;

    const unsigned aFragBase = (unsigned)__cvta_generic_to_shared(
        &AsH[(wm * 64 + (lane & 15)) * ASTR + ((lane >> 4) << 3)]);
    const unsigned bFragBase = (unsigned)__cvta_generic_to_shared(
        &BsH[(lane & 15) * BSTR + wn * 32 + ((lane >> 4) << 3)]);

    float acc[4][4][4];
#pragma unroll
    for (int mt = 0; mt < 4; mt++)
#pragma unroll
        for (int nt = 0; nt < 4; nt++)
#pragma unroll
            for (int r = 0; r < 4; r++) acc[mt][nt][r] = 0.f;

    const int nk = K / GBK;   // 8

    // prologue: stages 0..2
#pragma unroll
    for (int s = 0; s < STAGES - 1; s++) {
        const int k0 = s * GBK;
        cp_async16(asBase + s * ABUF + aOff0, Aptr + (size_t)a_r0 * K + k0 + a_c0);
        cp_async16(asBase + s * ABUF + aOff1, Aptr + (size_t)a_r1 * K + k0 + a_c1);
        cp_async16(bsBase + s * BBUF + bOff0, Bptr + (size_t)(k0 + b_r0) * N + b_c0);
        cp_async16(bsBase + s * BBUF + bOff1, Bptr + (size_t)(k0 + b_r1) * N + b_c1);
        cp_commit();
    }
    asm volatile("cp.async.wait_group %0;" :: "n"(STAGES - 2));
    __syncthreads();

    int buf = 0;
    for (int kt = 0; kt < nk; kt++) {
        if (kt + STAGES - 1 < nk) {
            const int k0 = (kt + STAGES - 1) * GBK;
            const unsigned sb = (unsigned)((kt + STAGES - 1) & (STAGES - 1));
            cp_async16(asBase + sb * ABUF + aOff0, Aptr + (size_t)a_r0 * K + k0 + a_c0);
            cp_async16(asBase + sb * ABUF + aOff1, Aptr + (size_t)a_r1 * K + k0 + a_c1);
            cp_async16(bsBase + sb * BBUF + bOff0, Bptr + (size_t)(k0 + b_r0) * N + b_c0);
            cp_async16(bsBase + sb * BBUF + bOff1, Bptr + (size_t)(k0 + b_r1) * N + b_c1);
        }
        cp_commit();

        // compute stage buf: 2 k16 chunks
#pragma unroll
        for (int kc = 0; kc < 2; kc++) {
            unsigned af[4][4], bf[2][4];
#pragma unroll
            for (int mt = 0; mt < 4; mt++)
                ldsm4(af[mt], aFragBase + buf * ABUF + mt * (16 * ASTR * 2) + kc * 32);
#pragma unroll
            for (int db = 0; db < 2; db++)
                ldsm4t(bf[db], bFragBase + buf * BBUF + kc * (16 * BSTR * 2) + db * 32);
#pragma unroll
            for (int nt = 0; nt < 4; nt++) {
                const unsigned b0 = bf[nt >> 1][(nt & 1) * 2];
                const unsigned b1 = bf[nt >> 1][(nt & 1) * 2 + 1];
#pragma unroll
                for (int mt = 0; mt < 4; mt++)
                    mma_f16(acc[mt][nt], af[mt], b0, b1);
            }
        }

        asm volatile("cp.async.wait_group %0;" :: "n"(STAGES - 2));
        __syncthreads();
        buf = (buf + 1) & (STAGES - 1);
    }

#pragma unroll
    for (int mt = 0; mt < 4; mt++) {
        const int r0 = rowC + wm * 64 + mt * 16 + g;
#pragma unroll
        for (int nt = 0; nt < 4; nt++) {
            const int cc = colC + wn * 32 + nt * 8 + 2 * t;
            const float bb0 = bias[cc], bb1 = bias[cc + 1];
            if (OUT_HALF) {
                __half* C = (__half*)Cv;
                *(__half2*)&C[(size_t)r0 * N + cc] =
                    __floats2half2_rn(acc[mt][nt][0] + bb0, acc[mt][nt][1] + bb1);
                *(__half2*)&C[(size_t)(r0 + 8) * N + cc] =
                    __floats2half2_rn(acc[mt][nt][2] + bb0, acc[mt][nt][3] + bb1);
            } else {
                float* C = (float*)Cv;
                float2 o;
                o.x = acc[mt][nt][0] + bb0; o.y = acc[mt][nt][1] + bb1;
                *(float2*)&C[(size_t)r0 * N + cc] = o;
                o.x = acc[mt][nt][2] + bb0; o.y = acc[mt][nt][3] + bb1;
                *(float2*)&C[(size_t)(r0 + 8) * N + cc] = o;
            }
        }
    }
}

// ---------------------------------------------------------------------------
// FP16 tensor-core window attention: one CTA per (b, h), 4 warps.
// Warp-local softmax; P stored fp16 (no split — fp16 relative precision on
// softmax weights adds only ~1e-4 rel_err).
// ---------------------------------------------------------------------------
#define QSTR 40      // halves per q/k/v row (80B)
#define SCSTR 72     // halves per P row (144B)

__global__ __launch_bounds__(128) void attn_mma_kernel(
    const __half* __restrict__ qkv, const float* __restrict__ comb,
    __half* __restrict__ out)
{
    const int h = blockIdx.x;
    const int b = blockIdx.y;

    __shared__ __half qs[64][QSTR];
    __shared__ __half ks[64][QSTR];
    __shared__ __half vs[64][QSTR];
    __shared__ __half sch[64][SCSTR];

    const int tid  = threadIdx.x;
    const int lane = tid & 31;
    const int wid  = tid >> 5;
    const int g    = lane >> 2;
    const int t    = lane & 3;
    const float scale = 0.17677669529663687f;  // 32^-0.5

    const __half* base = qkv + (size_t)b * NSEQ * THREECD + h * DHEAD;
    for (int f = tid; f < NSEQ * 8; f += 128) {
        int n = f >> 3, c = (f & 7) << 2;
        const __half* row = base + (size_t)n * THREECD;
        *(uint2*)&qs[n][c] = *(const uint2*)(row + c);
        *(uint2*)&ks[n][c] = *(const uint2*)(row + CDIM + c);
        *(uint2*)&vs[n][c] = *(const uint2*)(row + 2 * CDIM + c);
    }
    for (int z = tid; z < 15 * QSTR; z += 128)
        vs[NSEQ + z / QSTR][z % QSTR] = __ushort_as_half(0);
    __syncthreads();

    const int row = wid * 16;

    // ---- QK^T
    float c_sc[7][4];
#pragma unroll
    for (int nt = 0; nt < 7; nt++)
#pragma unroll
        for (int r = 0; r < 4; r++) c_sc[nt][r] = 0.f;

    const unsigned qAddr = (unsigned)__cvta_generic_to_shared(
        &qs[row + (lane & 15)][(lane >> 4) << 3]);
    const unsigned kAddr = (unsigned)__cvta_generic_to_shared(
        &ks[(lane & 7) + ((lane >> 4) << 3)][((lane >> 3) & 1) << 3]);

#pragma unroll
    for (int kc = 0; kc < 2; kc++) {
        const int k0 = kc * 16;
        unsigned a[4];
        ldsm4(a, qAddr + k0 * 2);
        unsigned bf[4][4];
#pragma unroll
        for (int jb = 0; jb < 4; jb++)
            ldsm4(bf[jb], kAddr + (jb * 16 * QSTR + k0) * 2);
#pragma unroll
        for (int nt = 0; nt < 7; nt++) {
            const unsigned b0 = bf[nt >> 1][(nt & 1) * 2];
            const unsigned b1 = bf[nt >> 1][(nt & 1) * 2 + 1];
            mma_f16(c_sc[nt], a, b0, b1);
        }
    }

    // ---- epilogue: scale + comb, warp-local softmax
    const int r0 = row + g, r1 = r0 + 8;
    const float* cb = comb + ((size_t)(b & (NW - 1)) * NHEADS + h) * NSEQ * NSEQ;

    float mx0 = -1e30f, mx1 = -1e30f;
#pragma unroll
    for (int nt = 0; nt < 7; nt++) {
#pragma unroll
        for (int cx = 0; cx < 2; cx++) {
            const int cc = nt * 8 + 2 * t + cx;
            float v0 = (r0 < NSEQ && cc < NSEQ)
                     ? fmaf(c_sc[nt][cx], scale, cb[r0 * NSEQ + cc]) : -1e30f;
            float v1 = (r1 < NSEQ && cc < NSEQ)
                     ? fmaf(c_sc[nt][2 + cx], scale, cb[r1 * NSEQ + cc]) : -1e30f;
            c_sc[nt][cx] = v0;     mx0 = fmaxf(mx0, v0);
            c_sc[nt][2 + cx] = v1; mx1 = fmaxf(mx1, v1);
        }
    }
    mx0 = fmaxf(mx0, __shfl_xor_sync(0xffffffffu, mx0, 1));
    mx0 = fmaxf(mx0, __shfl_xor_sync(0xffffffffu, mx0, 2));
    mx1 = fmaxf(mx1, __shfl_xor_sync(0xffffffffu, mx1, 1));
    mx1 = fmaxf(mx1, __shfl_xor_sync(0xffffffffu, mx1, 2));

    float s0 = 0.f, s1 = 0.f;
#pragma unroll
    for (int nt = 0; nt < 7; nt++) {
#pragma unroll
        for (int cx = 0; cx < 2; cx++) {
            float e0 = __expf(c_sc[nt][cx] - mx0);
            float e1 = __expf(c_sc[nt][2 + cx] - mx1);
            c_sc[nt][cx] = e0;     s0 += e0;
            c_sc[nt][2 + cx] = e1; s1 += e1;
        }
    }
    s0 += __shfl_xor_sync(0xffffffffu, s0, 1);
    s0 += __shfl_xor_sync(0xffffffffu, s0, 2);
    s1 += __shfl_xor_sync(0xffffffffu, s1, 1);
    s1 += __shfl_xor_sync(0xffffffffu, s1, 2);
    const float inv0 = 1.f / s0, inv1 = 1.f / s1;

#pragma unroll
    for (int nt = 0; nt < 7; nt++) {
        const int cc = nt * 8 + 2 * t;
        float p00 = (cc     < NSEQ) ? c_sc[nt][0] * inv0 : 0.f;
        float p01 = (cc + 1 < NSEQ) ? c_sc[nt][1] * inv0 : 0.f;
        float p10 = (cc     < NSEQ) ? c_sc[nt][2] * inv1 : 0.f;
        float p11 = (cc + 1 < NSEQ) ? c_sc[nt][3] * inv1 : 0.f;
        *(__half2*)&sch[r0][cc] = __floats2half2_rn(p00, p01);
        *(__half2*)&sch[r1][cc] = __floats2half2_rn(p10, p11);
    }
    {
        const int cc = 56 + 2 * t;
        *(unsigned*)&sch[r0][cc] = 0u;
        *(unsigned*)&sch[r1][cc] = 0u;
    }
    __syncwarp();

    // ---- AV
    float c_o[4][4];
#pragma unroll
    for (int nt = 0; nt < 4; nt++)
#pragma unroll
        for (int r = 0; r < 4; r++) c_o[nt][r] = 0.f;

    const unsigned pAddr = (unsigned)__cvta_generic_to_shared(
        &sch[row + (lane & 15)][(lane >> 4) << 3]);
    const unsigned vAddr = (unsigned)__cvta_generic_to_shared(
        &vs[lane & 15][(lane >> 4) << 3]);

#pragma unroll
    for (int kc = 0; kc < 4; kc++) {
        const int k0 = kc * 16;
        unsigned ap[4];
        ldsm4(ap, pAddr + k0 * 2);
        unsigned bf[2][4];
#pragma unroll
        for (int db = 0; db < 2; db++)
            ldsm4t(bf[db], vAddr + (k0 * QSTR + db * 16) * 2);
#pragma unroll
        for (int nt = 0; nt < 4; nt++) {
            const unsigned b0 = bf[nt >> 1][(nt & 1) * 2];
            const unsigned b1 = bf[nt >> 1][(nt & 1) * 2 + 1];
            mma_f16(c_o[nt], ap, b0, b1);
        }
    }

    __half* obase = out + (size_t)b * NSEQ * CDIM + h * DHEAD;
#pragma unroll
    for (int nt = 0; nt < 4; nt++) {
        const int dd = nt * 8 + 2 * t;
        if (r0 < NSEQ)
            *(__half2*)&obase[(size_t)r0 * CDIM + dd] =
                __floats2half2_rn(c_o[nt][0], c_o[nt][1]);
        if (r1 < NSEQ)
            *(__half2*)&obase[(size_t)r1 * CDIM + dd] =
                __floats2half2_rn(c_o[nt][2], c_o[nt][3]);
    }
}

// ---------------------------------------------------------------------------
extern "C" void kernel_launch(void* const* d_in, const int* in_sizes, int n_in,
                              void* d_out, int out_size)
{
    const float* x          = (const float*)d_in[0];
    const float* mask       = (const float*)d_in[1];
    const float* qkv_w      = (const float*)d_in[2];
    const float* qkv_b      = (const float*)d_in[3];
    const float* proj_w     = (const float*)d_in[4];
    const float* proj_b     = (const float*)d_in[5];
    const float* bias_table = (const float*)d_in[6];
    float* out = (float*)d_out;

    __half *xh, *wqkvh, *wprojh, *qkvh, *aoh;
    float *comb_ptr;
    cudaGetSymbolAddress((void**)&xh, g_xh);
    cudaGetSymbolAddress((void**)&wqkvh, g_wqkvh);
    cudaGetSymbolAddress((void**)&wprojh, g_wprojh);
    cudaGetSymbolAddress((void**)&qkvh, g_qkvh);
    cudaGetSymbolAddress((void**)&aoh, g_aoh);
    cudaGetSymbolAddress((void**)&comb_ptr, g_comb);

    static bool attr_set = false;
    if (!attr_set) {
        cudaFuncSetAttribute(gemm_f16_kernel<true>,
                             cudaFuncAttributeMaxDynamicSharedMemorySize, GEMM_SMEM);
        cudaFuncSetAttribute(gemm_f16_kernel<false>,
                             cudaFuncAttributeMaxDynamicSharedMemorySize, GEMM_SMEM);
        attr_set = true;
    }

    const int M = B_TOT * NSEQ;  // 100352

    // 0) fused prepass
    prepass_kernel<<<NB_TOTAL, 256>>>(
        (const float4*)x, (uint2*)xh,
        (const float4*)qkv_w, (uint2*)wqkvh,
        (const float4*)proj_w, (uint2*)wprojh,
        mask, bias_table, comb_ptr);
    // 1) qkv = x @ qkv_w + qkv_b  -> fp16
    {
        dim3 grid(THREECD / GBN, M / GBM);
        gemm_f16_kernel<true><<<grid, 256, GEMM_SMEM>>>(xh, wqkvh, qkv_b, qkvh,
                                                        M, CDIM, THREECD);
    }
    // 2) window attention -> fp16
    {
        dim3 grid(NHEADS, B_TOT);
        attn_mma_kernel<<<grid, 128>>>(qkvh, comb_ptr, aoh);
    }
    // 3) out = attnout @ proj_w + proj_b -> fp32
    {
        dim3 grid(CDIM / GBN, M / GBM);
        gemm_f16_kernel<false><<<grid, 256, GEMM_SMEM>>>(aoh, wprojh, proj_b, out,
                                                         M, CDIM, CDIM);
    }
}